// round 1
// baseline (speedup 1.0000x reference)
#include <cuda_runtime.h>
#include <math.h>

#define Bx    256
#define OBSx  256
#define DINx  512
#define Dx    1024
#define Mx    32
#define HIDx  16
#define NSYx  64
#define ITERSx 4
#define SYNCHx 2080
#define DMx   (Dx * Mx)          // 32768
#define BDMx  (Bx * Dx * Mx)     // 8388608

// ---------------- scratch (static device globals, no allocation) ----------------
__device__ float g_st[BDMx];
__device__ float g_at[BDMx];
__device__ float g_f[Bx * DINx];
__device__ float g_pre[Bx * (DINx + Dx)];
__device__ float g_y[Bx * 2 * Dx];
__device__ float g_h1[Bx * Dx];
__device__ float g_w1t[Dx * 2 * HIDx * Mx];   // [d][m][h], h fast
__device__ float g_w2t[Dx * HIDx * 2];        // [d][h][c]
__device__ float g_decay[Mx * SYNCHx];
__device__ float g_invden[SYNCHx];
__device__ int   g_tri_i[SYNCHx];
__device__ int   g_tri_j[SYNCHx];
__device__ int   g_dones[Bx];

__device__ __forceinline__ float sigf(float x) { return 1.0f / (1.0f + expf(-x)); }

// ---------------- dones dtype auto-detect + convert ----------------
// bool -> 1 byte/elem; int32 -> 4 bytes; float32 -> 4 bytes. First 256 bytes
// are safe to read in every layout. Nonzero float 1.0f has bytes {0,0,0x80,0x3F}.
__global__ void k_dones(const unsigned char* raw) {
    __shared__ int mode;
    if (threadIdx.x == 0) {
        bool nzoff = false, floatlike = true, anynz = false;
        for (int i = 0; i < Bx; i++) {
            unsigned char v = raw[i];
            if (v) {
                anynz = true;
                int r = i & 3;
                if (r != 0) nzoff = true;
                bool okf = (r == 2 && v == 0x80) || (r == 3 && v == 0x3F);
                if (!okf) floatlike = false;
            }
        }
        // 2=float32, 0=bool bytes, 1=int32 (also covers the all-zero case)
        mode = (nzoff && floatlike && anynz) ? 2 : (nzoff ? 0 : 1);
    }
    __syncthreads();
    int b = threadIdx.x;
    int m = mode, v;
    if (m == 0)      v = (raw[b] != 0);
    else if (m == 1) v = (((const int*)raw)[b] != 0);
    else             v = (((const float*)raw)[b] != 0.0f);
    g_dones[b] = v;
}

// ---------------- decay table + triu indices ----------------
__global__ void k_decay(const float* __restrict__ dp) {
    int s = blockIdx.x * blockDim.x + threadIdx.x;
    if (s >= SYNCHx) return;
    float c = fminf(fmaxf(dp[s], 0.0f), 4.0f);
    float sum = 0.0f;
    for (int m = 0; m < Mx; m++) {
        float v = expf(-(float)(Mx - 1 - m) * c);
        g_decay[m * SYNCHx + s] = v;
        sum += v;
    }
    g_invden[s] = rsqrtf(sum);
    int i = 0, base = 0;
    while (s >= base + (NSYx - i)) { base += NSYx - i; i++; }
    g_tri_i[s] = i;
    g_tri_j[s] = i + (s - base);
}

// ---------------- reset traces with dones ----------------
__global__ void k_init(const float* __restrict__ st_in, const float* __restrict__ at_in,
                       const float* __restrict__ start_st, const float* __restrict__ start_at) {
    int idx = blockIdx.x * blockDim.x + threadIdx.x;
    if (idx >= BDMx) return;
    int b = idx >> 15;        // / DMx
    int dm = idx & (DMx - 1);
    bool r = g_dones[b] != 0;
    g_st[idx] = r ? start_st[dm] : st_in[idx];
    g_at[idx] = r ? start_at[dm] : at_in[idx];
}

// ---------------- transpose nlm weights to d-major ----------------
__global__ void k_wt(const float* __restrict__ w1, const float* __restrict__ w2) {
    int idx = blockIdx.x * blockDim.x + threadIdx.x;
    if (idx < Dx * Mx * 2 * HIDx) {
        int d = idx >> 10;            // / 1024
        int mh = idx & 1023;          // m*32+h
        g_w1t[idx] = w1[mh * Dx + d]; // in: [(m*2H)+h][d]
    }
    if (idx < Dx * HIDx * 2) {
        int d = idx >> 5;
        int hc = idx & 31;            // h*2+c
        g_w2t[idx] = w2[hc * Dx + d];
    }
}

// ---------------- generic SGEMM: C = A(MrxK) @ W(KxN) + bias ----------------
// BM=BN=64, BK=16, 256 threads, 4x4 per thread. All dims are exact multiples.
__global__ void k_sgemm(const float* __restrict__ A, const float* __restrict__ W,
                        const float* __restrict__ bias, float* __restrict__ C,
                        int Mr, int N, int K) {
    __shared__ float As[16][64];
    __shared__ float Bs[16][64];
    int tid = threadIdx.x;
    int tx = tid & 15, ty = tid >> 4;
    int row0 = blockIdx.y * 64, col0 = blockIdx.x * 64;
    float acc[4][4];
#pragma unroll
    for (int i = 0; i < 4; i++)
#pragma unroll
        for (int j = 0; j < 4; j++) acc[i][j] = 0.0f;

    int ar = tid >> 2;          // 0..63 row in tile
    int akq = (tid & 3) * 4;    // k quad
    int bkk = tid >> 4;         // 0..15
    int bc = (tid & 15) * 4;    // col quad

    for (int k0 = 0; k0 < K; k0 += 16) {
        float4 av = *(const float4*)&A[(size_t)(row0 + ar) * K + k0 + akq];
        As[akq + 0][ar] = av.x;
        As[akq + 1][ar] = av.y;
        As[akq + 2][ar] = av.z;
        As[akq + 3][ar] = av.w;
        float4 bv = *(const float4*)&W[(size_t)(k0 + bkk) * N + col0 + bc];
        *(float4*)&Bs[bkk][bc] = bv;
        __syncthreads();
#pragma unroll
        for (int kk = 0; kk < 16; kk++) {
            float4 a4 = *(const float4*)&As[kk][ty * 4];
            float4 b4 = *(const float4*)&Bs[kk][tx * 4];
            float ar4[4] = {a4.x, a4.y, a4.z, a4.w};
            float br4[4] = {b4.x, b4.y, b4.z, b4.w};
#pragma unroll
            for (int i = 0; i < 4; i++)
#pragma unroll
                for (int j = 0; j < 4; j++) acc[i][j] += ar4[i] * br4[j];
        }
        __syncthreads();
    }
#pragma unroll
    for (int i = 0; i < 4; i++) {
        int r = row0 + ty * 4 + i;
#pragma unroll
        for (int j = 0; j < 4; j++) {
            int c = col0 + tx * 4 + j;
            C[(size_t)r * N + c] = acc[i][j] + bias[c];
        }
    }
}

// ---------------- fused GLU + LayerNorm over a row ----------------
// y: (B, 2*halfN). out[row*rs + c*cs] = LN(a*sigmoid(g))
__global__ void k_glu_ln(const float* __restrict__ y, int halfN,
                         const float* __restrict__ sc, const float* __restrict__ bi,
                         float* __restrict__ out, int rs, int cs) {
    __shared__ float v[1024];
    __shared__ float red_s[8], red_q[8];
    int row = blockIdx.x, tid = threadIdx.x;
    const float* yr = y + (size_t)row * 2 * halfN;
    float sum = 0.0f, sq = 0.0f;
    for (int c = tid; c < halfN; c += 256) {
        float a = yr[c];
        float g = yr[halfN + c];
        float val = a * sigf(g);
        v[c] = val;
        sum += val;
        sq += val * val;
    }
#pragma unroll
    for (int o = 16; o > 0; o >>= 1) {
        sum += __shfl_xor_sync(0xffffffffu, sum, o);
        sq  += __shfl_xor_sync(0xffffffffu, sq, o);
    }
    int w = tid >> 5;
    if ((tid & 31) == 0) { red_s[w] = sum; red_q[w] = sq; }
    __syncthreads();
    if (tid == 0) {
        float ts = 0.0f, tq = 0.0f;
        for (int i = 0; i < 8; i++) { ts += red_s[i]; tq += red_q[i]; }
        red_s[0] = ts; red_q[0] = tq;
    }
    __syncthreads();
    float invN = 1.0f / (float)halfN;
    float mean = red_s[0] * invN;
    float var = red_q[0] * invN - mean * mean;
    float inv = rsqrtf(var + 1e-6f);
    for (int c = tid; c < halfN; c += 256)
        out[(size_t)row * rs + (size_t)c * cs] = (v[c] - mean) * inv * sc[c] + bi[c];
}

// ---------------- build pre = [f | at_last] ----------------
__global__ void k_gather(int physlast) {
    int idx = blockIdx.x * blockDim.x + threadIdx.x;
    if (idx >= Bx * (DINx + Dx)) return;
    int b = idx / (DINx + Dx);
    int c = idx - b * (DINx + Dx);
    float val;
    if (c < DINx) val = g_f[b * DINx + c];
    else          val = g_at[(size_t)b * DMx + (c - DINx) * Mx + physlast];
    g_pre[idx] = val;
}

// ---------------- NLM: per (b,d) 32->32 GLU 16 -> 2 GLU 1 ----------------
__global__ void k_nlm(int base, int slot,
                      const float* __restrict__ b1, const float* __restrict__ T1,
                      const float* __restrict__ b2, const float* __restrict__ T2) {
    __shared__ float w1[1024];
    __shared__ float w2[32];
    __shared__ float bb1[32];
    __shared__ float bb2[2];
    __shared__ float invT[2];
    int d = blockIdx.x, tid = threadIdx.x;
    for (int t = tid; t < 1024; t += 256) w1[t] = g_w1t[d * 1024 + t];
    if (tid < 32) { w2[tid] = g_w2t[d * 32 + tid]; bb1[tid] = b1[d * 32 + tid]; }
    if (tid < 2)  bb2[tid] = b2[d * 2 + tid];
    if (tid == 0) { invT[0] = 1.0f / T1[0]; invT[1] = 1.0f / T2[0]; }
    __syncthreads();

    int b = tid;
    const float* sp = g_st + (size_t)b * DMx + d * Mx;
    float s[32];
#pragma unroll
    for (int p = 0; p < 32; p += 4) {
        float4 t4 = *(const float4*)(sp + p);
        s[p] = t4.x; s[p + 1] = t4.y; s[p + 2] = t4.z; s[p + 3] = t4.w;
    }
    float x[32];
#pragma unroll
    for (int h = 0; h < 32; h++) x[h] = bb1[h];
#pragma unroll
    for (int m = 0; m < 32; m++) {
        float a = s[(m + base) & 31];
#pragma unroll
        for (int h = 0; h < 32; h++) x[h] += a * w1[m * 32 + h];
    }
    float iT1 = invT[0], iT2 = invT[1];
    float y0 = bb2[0], y1 = bb2[1];
#pragma unroll
    for (int h = 0; h < 16; h++) {
        float u = (x[h] * iT1) * sigf(x[h + 16] * iT1);
        y0 += u * w2[h * 2 + 0];
        y1 += u * w2[h * 2 + 1];
    }
    float r = (y0 * iT2) * sigf(y1 * iT2);
    g_at[(size_t)b * DMx + d * Mx + slot] = r;
}

// ---------------- synchrony ----------------
__global__ void k_synch(int base, float* __restrict__ out) {
    __shared__ float S[Mx * NSYx]; // [m_logical][j]
    int b = blockIdx.x, tid = threadIdx.x;
    for (int t = tid; t < Mx * NSYx; t += 256) {
        int mp = t & 31, j = t >> 5;
        float val = g_at[(size_t)b * DMx + (Dx - NSYx + j) * Mx + mp];
        int ml = (mp - base + 32) & 31;
        S[ml * NSYx + j] = val;
    }
    __syncthreads();
    for (int s = tid; s < SYNCHx; s += 256) {
        int ti = g_tri_i[s], tj = g_tri_j[s];
        float acc = 0.0f;
#pragma unroll
        for (int m = 0; m < Mx; m++)
            acc += g_decay[m * SYNCHx + s] * S[m * NSYx + ti] * S[m * NSYx + tj];
        out[(size_t)b * SYNCHx + s] = acc * g_invden[s];
    }
}

// ---------------- final un-ring copy to d_out ----------------
__global__ void k_final(float* __restrict__ out) {
    int idx = blockIdx.x * blockDim.x + threadIdx.x;
    if (idx >= BDMx) return;
    int m = idx & 31;
    int src = (idx & ~31) | ((m + ITERSx) & 31);
    out[idx] = g_st[src];
    out[BDMx + idx] = g_at[src];
}

// =====================================================================
extern "C" void kernel_launch(void* const* d_in, const int* in_sizes, int n_in,
                              void* d_out, int out_size) {
    (void)in_sizes; (void)n_in; (void)out_size;
    const float* obs      = (const float*)d_in[0];
    const unsigned char* dones_raw = (const unsigned char*)d_in[1];
    const float* st_in    = (const float*)d_in[3];
    const float* at_in    = (const float*)d_in[4];
    const float* start_st = (const float*)d_in[5];
    const float* start_at = (const float*)d_in[6];
    const float* bb_w1    = (const float*)d_in[7];
    const float* bb_b1    = (const float*)d_in[8];
    const float* ln1s     = (const float*)d_in[9];
    const float* ln1b     = (const float*)d_in[10];
    const float* bb_w2    = (const float*)d_in[11];
    const float* bb_b2    = (const float*)d_in[12];
    const float* ln2s     = (const float*)d_in[13];
    const float* ln2b     = (const float*)d_in[14];
    const float* syn_w1   = (const float*)d_in[15];
    const float* syn_b1   = (const float*)d_in[16];
    const float* sln1s    = (const float*)d_in[17];
    const float* sln1b    = (const float*)d_in[18];
    const float* syn_w2   = (const float*)d_in[19];
    const float* syn_b2   = (const float*)d_in[20];
    const float* sln2s    = (const float*)d_in[21];
    const float* sln2b    = (const float*)d_in[22];
    const float* nlm1_w   = (const float*)d_in[23];
    const float* nlm1_b   = (const float*)d_in[24];
    const float* nlm1_T   = (const float*)d_in[25];
    const float* nlm2_w   = (const float*)d_in[26];
    const float* nlm2_b   = (const float*)d_in[27];
    const float* nlm2_T   = (const float*)d_in[28];
    const float* decay_p  = (const float*)d_in[29];
    float* out = (float*)d_out;

    void *p_st, *p_f, *p_pre, *p_y, *p_h1;
    cudaGetSymbolAddress(&p_st, g_st);
    cudaGetSymbolAddress(&p_f, g_f);
    cudaGetSymbolAddress(&p_pre, g_pre);
    cudaGetSymbolAddress(&p_y, g_y);
    cudaGetSymbolAddress(&p_h1, g_h1);
    float* gst = (float*)p_st;
    float* gf  = (float*)p_f;
    float* gpre = (float*)p_pre;
    float* gy  = (float*)p_y;
    float* gh1 = (float*)p_h1;

    k_dones<<<1, 256>>>(dones_raw);
    k_decay<<<(SYNCHx + 255) / 256, 256>>>(decay_p);
    k_init<<<BDMx / 256, 256>>>(st_in, at_in, start_st, start_at);
    k_wt<<<(Dx * 1024 + 255) / 256, 256>>>(nlm1_w, nlm2_w);

    // backbone
    k_sgemm<<<dim3(2 * DINx / 64, Bx / 64), 256>>>(obs, bb_w1, bb_b1, gy, Bx, 2 * DINx, OBSx);
    k_glu_ln<<<Bx, 256>>>(gy, DINx, ln1s, ln1b, gf, DINx, 1);
    k_sgemm<<<dim3(2 * DINx / 64, Bx / 64), 256>>>(gf, bb_w2, bb_b2, gy, Bx, 2 * DINx, DINx);
    k_glu_ln<<<Bx, 256>>>(gy, DINx, ln2s, ln2b, gf, DINx, 1);

    for (int i = 0; i < ITERSx; i++) {
        int physlast = (Mx - 1 + i) & 31;
        k_gather<<<(Bx * (DINx + Dx)) / 256, 256>>>(physlast);
        k_sgemm<<<dim3(2 * Dx / 64, Bx / 64), 256>>>(gpre, syn_w1, syn_b1, gy, Bx, 2 * Dx, DINx + Dx);
        k_glu_ln<<<Bx, 256>>>(gy, Dx, sln1s, sln1b, gh1, Dx, 1);
        k_sgemm<<<dim3(2 * Dx / 64, Bx / 64), 256>>>(gh1, syn_w2, syn_b2, gy, Bx, 2 * Dx, Dx);
        // write h directly into the st ring slot i (strided output)
        k_glu_ln<<<Bx, 256>>>(gy, Dx, sln2s, sln2b, gst + i, DMx, Mx);
        k_nlm<<<Dx, 256>>>(i + 1, i, nlm1_b, nlm1_T, nlm2_b, nlm2_T);
        if (i == ITERSx - 1)
            k_synch<<<Bx, 256>>>(ITERSx, out + 2 * (size_t)BDMx);
    }
    k_final<<<BDMx / 256, 256>>>(out);
}

// round 3
// speedup vs baseline: 2.1374x; 2.1374x over previous
#include <cuda_runtime.h>
#include <cuda_bf16.h>
#include <math.h>
#include <stdint.h>

#define Bx    256
#define OBSx  256
#define DINx  512
#define Dx    1024
#define Mx    32
#define HIDx  16
#define NSYx  64
#define ITERSx 4
#define SYNCHx 2080
#define DMx   (Dx * Mx)          // 32768
#define BDMx  (Bx * Dx * Mx)     // 8388608

// ---------------- scratch (static device globals, no allocation) ----------------
__device__ float g_st[BDMx];
__device__ float g_at[BDMx];
__device__ float g_y[Bx * 2 * Dx];
__device__ float g_w1t[Dx * 2 * HIDx * Mx];   // [d][m][h], h fast (NLM)
__device__ float g_w2t[Dx * HIDx * 2];        // [d][h][c]   (NLM)
__device__ float g_decay[Mx * SYNCHx];
__device__ float g_invden[SYNCHx];
__device__ int   g_tri_i[SYNCHx];
__device__ int   g_tri_j[SYNCHx];
__device__ int   g_dones[Bx];

// bf16 hi/lo split buffers
__device__ __align__(256) __nv_bfloat16 g_obshi[Bx * OBSx];
__device__ __align__(256) __nv_bfloat16 g_obslo[Bx * OBSx];
__device__ __align__(256) __nv_bfloat16 g_fhi[Bx * DINx];
__device__ __align__(256) __nv_bfloat16 g_flo[Bx * DINx];
__device__ __align__(256) __nv_bfloat16 g_prehi[Bx * (DINx + Dx)];
__device__ __align__(256) __nv_bfloat16 g_prelo[Bx * (DINx + Dx)];
__device__ __align__(256) __nv_bfloat16 g_h1hi[Bx * Dx];
__device__ __align__(256) __nv_bfloat16 g_h1lo[Bx * Dx];
// weights transposed to [N][K] bf16 hi/lo
__device__ __align__(256) __nv_bfloat16 g_wb1hi[1024 * 256];
__device__ __align__(256) __nv_bfloat16 g_wb1lo[1024 * 256];
__device__ __align__(256) __nv_bfloat16 g_wb2hi[1024 * 512];
__device__ __align__(256) __nv_bfloat16 g_wb2lo[1024 * 512];
__device__ __align__(256) __nv_bfloat16 g_ws1hi[2048 * 1536];
__device__ __align__(256) __nv_bfloat16 g_ws1lo[2048 * 1536];
__device__ __align__(256) __nv_bfloat16 g_ws2hi[2048 * 1024];
__device__ __align__(256) __nv_bfloat16 g_ws2lo[2048 * 1024];

__device__ __forceinline__ float sigf(float x) { return 1.0f / (1.0f + expf(-x)); }

__device__ __forceinline__ void split2(float v, __nv_bfloat16* h, __nv_bfloat16* l) {
    __nv_bfloat16 hh = __float2bfloat16(v);
    *h = hh;
    *l = __float2bfloat16(v - __bfloat162float(hh));
}

// ================= PTX helpers (portable sm_80+ subset) =================
__device__ __forceinline__ uint32_t smem_u32(const void* p) {
    uint32_t a;
    asm("{ .reg .u64 t; cvta.to.shared.u64 t, %1; cvt.u32.u64 %0, t; }" : "=r"(a) : "l"(p));
    return a;
}

#define SW128(off) ((off) ^ (((off) >> 3) & 0x70))

#define CP_ASYNC16(dst, src) \
    asm volatile("cp.async.cg.shared.global [%0], [%1], 16;" :: "r"(dst), "l"(src))
#define CP_COMMIT()  asm volatile("cp.async.commit_group;" ::: "memory")
#define CP_WAIT(n)   asm volatile("cp.async.wait_group %0;" :: "n"(n) : "memory")

#define LDSM4(r, addr) \
    asm volatile("ldmatrix.sync.aligned.m8n8.x4.shared.b16 {%0,%1,%2,%3}, [%4];" \
        : "=r"((r)[0]), "=r"((r)[1]), "=r"((r)[2]), "=r"((r)[3]) : "r"(addr))

#define MMA16816(acc, a, b0, b1) \
    asm volatile("mma.sync.aligned.m16n8k16.row.col.f32.bf16.bf16.f32 " \
        "{%0,%1,%2,%3}, {%4,%5,%6,%7}, {%8,%9}, {%0,%1,%2,%3};" \
        : "+f"((acc)[0]), "+f"((acc)[1]), "+f"((acc)[2]), "+f"((acc)[3]) \
        : "r"((a)[0]), "r"((a)[1]), "r"((a)[2]), "r"((a)[3]), "r"(b0), "r"(b1))

// ================= split-bf16 HMMA GEMM =================
// C[Mr,N] = (Ahi+Alo)[Mr,K] @ ((Bhi+Blo)[N,K])^T + bias, fp32 accumulate.
// CTA tile 64x64, BK=64, 8 warps (warp_m in {0,1} x warp_n in {0..3}),
// each warp computes 32m x 16n. Double-buffered cp.async, SW128 smem.
#define GBUF_BYTES 32768   // Ahi 8K | Alo 8K | Bhi 8K | Blo 8K
__global__ void __launch_bounds__(256) k_tgemm(
    const __nv_bfloat16* __restrict__ Ahi, const __nv_bfloat16* __restrict__ Alo,
    const __nv_bfloat16* __restrict__ Bhi, const __nv_bfloat16* __restrict__ Blo,
    const float* __restrict__ bias, float* __restrict__ C, int K, int N)
{
    extern __shared__ char smem_raw[];
    uint32_t sbase = smem_u32(smem_raw);
    uint32_t abase = (sbase + 1023u) & ~1023u;

    int tid = threadIdx.x;
    int lane = tid & 31;
    int wid = tid >> 5;
    int warp_m = wid & 1;
    int warp_n = wid >> 1;
    int row0 = blockIdx.y * 64;
    int col0 = blockIdx.x * 64;
    int NC = K >> 6;

    float acc[2][2][4];
#pragma unroll
    for (int i = 0; i < 2; i++)
#pragma unroll
        for (int j = 0; j < 2; j++)
#pragma unroll
            for (int q = 0; q < 4; q++) acc[i][j][q] = 0.0f;

    // loader: each of 4 matrices is 64 rows x 64 bf16 (8 x 16B chunks/row)
    auto load_chunk = [&](int buf, int k0) {
        uint32_t bb = abase + buf * GBUF_BYTES;
#pragma unroll
        for (int i = 0; i < 2; i++) {
            int u = tid + i * 256;            // 0..511
            int r = u >> 3, ch = u & 7;
            uint32_t soff = SW128((uint32_t)(r * 128 + ch * 16));
            size_t goA = (size_t)(row0 + r) * K + k0 + ch * 8;
            size_t goB = (size_t)(col0 + r) * K + k0 + ch * 8;
            CP_ASYNC16(bb + soff,          Ahi + goA);
            CP_ASYNC16(bb + 8192 + soff,   Alo + goA);
            CP_ASYNC16(bb + 16384 + soff,  Bhi + goB);
            CP_ASYNC16(bb + 24576 + soff,  Blo + goB);
        }
    };

    load_chunk(0, 0);
    CP_COMMIT();

    // ldmatrix lane address patterns (constant across k-steps except col)
    int a_r = warp_m * 32 + (lane & 15);          // + mf*16
    int a_csel = (lane >> 4) << 3;                // 0 or 8 (k offset)
    int b_r = warp_n * 16 + (lane & 7) + ((lane >> 4) << 3);
    int b_csel = ((lane >> 3) & 1) << 3;

    for (int c = 0; c < NC; c++) {
        if (c + 1 < NC) { load_chunk((c + 1) & 1, (c + 1) * 64); CP_COMMIT(); CP_WAIT(1); }
        else            { CP_WAIT(0); }
        __syncthreads();

        uint32_t bb = abase + (c & 1) * GBUF_BYTES;
#pragma unroll
        for (int kk = 0; kk < 4; kk++) {
            int k0 = kk * 16;
            uint32_t ah[2][4], al[2][4], bh[4], bl[4];
#pragma unroll
            for (int mf = 0; mf < 2; mf++) {
                uint32_t off = SW128((uint32_t)((a_r + mf * 16) * 128 + (k0 + a_csel) * 2));
                LDSM4(ah[mf], bb + off);
                LDSM4(al[mf], bb + 8192 + off);
            }
            {
                uint32_t off = SW128((uint32_t)(b_r * 128 + (k0 + b_csel) * 2));
                LDSM4(bh, bb + 16384 + off);
                LDSM4(bl, bb + 24576 + off);
            }
#pragma unroll
            for (int mf = 0; mf < 2; mf++) {
#pragma unroll
                for (int nf = 0; nf < 2; nf++) {
                    MMA16816(acc[mf][nf], ah[mf], bh[2 * nf], bh[2 * nf + 1]);
                    MMA16816(acc[mf][nf], ah[mf], bl[2 * nf], bl[2 * nf + 1]);
                    MMA16816(acc[mf][nf], al[mf], bh[2 * nf], bh[2 * nf + 1]);
                }
            }
        }
        __syncthreads();
    }

    // epilogue
    int gid = lane >> 2, tig = lane & 3;
#pragma unroll
    for (int mf = 0; mf < 2; mf++) {
#pragma unroll
        for (int nf = 0; nf < 2; nf++) {
            int r = row0 + warp_m * 32 + mf * 16 + gid;
            int cc = col0 + warp_n * 16 + nf * 8 + tig * 2;
            float2 b01 = *(const float2*)&bias[cc];
            float2 o0 = { acc[mf][nf][0] + b01.x, acc[mf][nf][1] + b01.y };
            float2 o1 = { acc[mf][nf][2] + b01.x, acc[mf][nf][3] + b01.y };
            *(float2*)&C[(size_t)r * N + cc] = o0;
            *(float2*)&C[(size_t)(r + 8) * N + cc] = o1;
        }
    }
}

// ---------------- dones dtype auto-detect + convert ----------------
__global__ void k_dones(const unsigned char* raw) {
    __shared__ int mode;
    if (threadIdx.x == 0) {
        bool nzoff = false, floatlike = true, anynz = false;
        for (int i = 0; i < Bx; i++) {
            unsigned char v = raw[i];
            if (v) {
                anynz = true;
                int r = i & 3;
                if (r != 0) nzoff = true;
                bool okf = (r == 2 && v == 0x80) || (r == 3 && v == 0x3F);
                if (!okf) floatlike = false;
            }
        }
        mode = (nzoff && floatlike && anynz) ? 2 : (nzoff ? 0 : 1);
    }
    __syncthreads();
    int b = threadIdx.x;
    int m = mode, v;
    if (m == 0)      v = (raw[b] != 0);
    else if (m == 1) v = (((const int*)raw)[b] != 0);
    else             v = (((const float*)raw)[b] != 0.0f);
    g_dones[b] = v;
}

// ---------------- decay table + triu indices ----------------
__global__ void k_decay(const float* __restrict__ dp) {
    int s = blockIdx.x * blockDim.x + threadIdx.x;
    if (s >= SYNCHx) return;
    float c = fminf(fmaxf(dp[s], 0.0f), 4.0f);
    float sum = 0.0f;
    for (int m = 0; m < Mx; m++) {
        float v = expf(-(float)(Mx - 1 - m) * c);
        g_decay[m * SYNCHx + s] = v;
        sum += v;
    }
    g_invden[s] = rsqrtf(sum);
    int i = 0, base = 0;
    while (s >= base + (NSYx - i)) { base += NSYx - i; i++; }
    g_tri_i[s] = i;
    g_tri_j[s] = i + (s - base);
}

// ---------------- reset traces ----------------
__global__ void k_init(const float* __restrict__ st_in, const float* __restrict__ at_in,
                       const float* __restrict__ start_st, const float* __restrict__ start_at) {
    int idx = blockIdx.x * blockDim.x + threadIdx.x;
    if (idx >= BDMx) return;
    int b = idx >> 15;
    int dm = idx & (DMx - 1);
    bool r = g_dones[b] != 0;
    g_st[idx] = r ? start_st[dm] : st_in[idx];
    g_at[idx] = r ? start_at[dm] : at_in[idx];
}

// ---------------- NLM weights to d-major ----------------
__global__ void k_wt(const float* __restrict__ w1, const float* __restrict__ w2) {
    int idx = blockIdx.x * blockDim.x + threadIdx.x;
    if (idx < Dx * Mx * 2 * HIDx) {
        int d = idx >> 10;
        int mh = idx & 1023;
        g_w1t[idx] = w1[mh * Dx + d];
    }
    if (idx < Dx * HIDx * 2) {
        int d = idx >> 5;
        int hc = idx & 31;
        g_w2t[idx] = w2[hc * Dx + d];
    }
}

// ---------------- weight transpose + bf16 split: [K][N] -> [N][K] hi/lo ----------------
__global__ void k_tsplit(const float* __restrict__ W, int K, int N,
                         __nv_bfloat16* __restrict__ Ohi, __nv_bfloat16* __restrict__ Olo) {
    __shared__ float t[32][33];
    int k0 = blockIdx.x * 32, n0 = blockIdx.y * 32;
    int tx = threadIdx.x & 31, ty = threadIdx.x >> 5;
    for (int i = ty; i < 32; i += 8)
        t[i][tx] = W[(size_t)(k0 + i) * N + n0 + tx];
    __syncthreads();
    for (int i = ty; i < 32; i += 8) {
        float v = t[tx][i];
        size_t o = (size_t)(n0 + i) * K + k0 + tx;
        __nv_bfloat16 h, l;
        split2(v, &h, &l);
        Ohi[o] = h; Olo[o] = l;
    }
}

// ---------------- obs -> bf16 hi/lo ----------------
__global__ void k_split_obs(const float* __restrict__ x) {
    int i = blockIdx.x * blockDim.x + threadIdx.x;
    if (i >= Bx * OBSx) return;
    split2(x[i], &g_obshi[i], &g_obslo[i]);
}

// ---------------- fused GLU + LayerNorm ----------------
// If ohi != null: write bf16 hi/lo [row][halfN]; else write fp32 out[row*rs + c*cs].
__global__ void k_glu_ln(const float* __restrict__ y, int halfN,
                         const float* __restrict__ sc, const float* __restrict__ bi,
                         float* __restrict__ out, int rs, int cs,
                         __nv_bfloat16* __restrict__ ohi, __nv_bfloat16* __restrict__ olo) {
    __shared__ float v[1024];
    __shared__ float red_s[8], red_q[8];
    int row = blockIdx.x, tid = threadIdx.x;
    const float* yr = y + (size_t)row * 2 * halfN;
    float sum = 0.0f, sq = 0.0f;
    for (int c = tid; c < halfN; c += 256) {
        float a = yr[c];
        float g = yr[halfN + c];
        float val = a * sigf(g);
        v[c] = val;
        sum += val;
        sq += val * val;
    }
#pragma unroll
    for (int o = 16; o > 0; o >>= 1) {
        sum += __shfl_xor_sync(0xffffffffu, sum, o);
        sq  += __shfl_xor_sync(0xffffffffu, sq, o);
    }
    int w = tid >> 5;
    if ((tid & 31) == 0) { red_s[w] = sum; red_q[w] = sq; }
    __syncthreads();
    if (tid == 0) {
        float ts = 0.0f, tq = 0.0f;
        for (int i = 0; i < 8; i++) { ts += red_s[i]; tq += red_q[i]; }
        red_s[0] = ts; red_q[0] = tq;
    }
    __syncthreads();
    float invN = 1.0f / (float)halfN;
    float mean = red_s[0] * invN;
    float var = red_q[0] * invN - mean * mean;
    float inv = rsqrtf(var + 1e-6f);
    if (ohi) {
        for (int c = tid; c < halfN; c += 256) {
            float val = (v[c] - mean) * inv * sc[c] + bi[c];
            size_t o = (size_t)row * halfN + c;
            split2(val, &ohi[o], &olo[o]);
        }
    } else {
        for (int c = tid; c < halfN; c += 256)
            out[(size_t)row * rs + (size_t)c * cs] = (v[c] - mean) * inv * sc[c] + bi[c];
    }
}

// ---------------- pre = [f | at_last] -> bf16 hi/lo ----------------
__global__ void k_gather(int physlast) {
    int idx = blockIdx.x * blockDim.x + threadIdx.x;
    if (idx >= Bx * (DINx + Dx)) return;
    int b = idx / (DINx + Dx);
    int c = idx - b * (DINx + Dx);
    if (c < DINx) {
        g_prehi[idx] = g_fhi[b * DINx + c];
        g_prelo[idx] = g_flo[b * DINx + c];
    } else {
        float val = g_at[(size_t)b * DMx + (c - DINx) * Mx + physlast];
        split2(val, &g_prehi[idx], &g_prelo[idx]);
    }
}

// ---------------- NLM ----------------
__global__ void k_nlm(int base, int slot,
                      const float* __restrict__ b1, const float* __restrict__ T1,
                      const float* __restrict__ b2, const float* __restrict__ T2) {
    __shared__ float w1[1024];
    __shared__ float w2[32];
    __shared__ float bb1[32];
    __shared__ float bb2[2];
    __shared__ float invT[2];
    int d = blockIdx.x, tid = threadIdx.x;
    for (int t = tid; t < 1024; t += 256) w1[t] = g_w1t[d * 1024 + t];
    if (tid < 32) { w2[tid] = g_w2t[d * 32 + tid]; bb1[tid] = b1[d * 32 + tid]; }
    if (tid < 2)  bb2[tid] = b2[d * 2 + tid];
    if (tid == 0) { invT[0] = 1.0f / T1[0]; invT[1] = 1.0f / T2[0]; }
    __syncthreads();

    int b = tid;
    const float* sp = g_st + (size_t)b * DMx + d * Mx;
    float s[32];
#pragma unroll
    for (int p = 0; p < 32; p += 4) {
        float4 t4 = *(const float4*)(sp + p);
        s[p] = t4.x; s[p + 1] = t4.y; s[p + 2] = t4.z; s[p + 3] = t4.w;
    }
    float x[32];
#pragma unroll
    for (int h = 0; h < 32; h++) x[h] = bb1[h];
#pragma unroll
    for (int m = 0; m < 32; m++) {
        float a = s[(m + base) & 31];
#pragma unroll
        for (int h = 0; h < 32; h++) x[h] += a * w1[m * 32 + h];
    }
    float iT1 = invT[0], iT2 = invT[1];
    float y0 = bb2[0], y1 = bb2[1];
#pragma unroll
    for (int h = 0; h < 16; h++) {
        float u = (x[h] * iT1) * sigf(x[h + 16] * iT1);
        y0 += u * w2[h * 2 + 0];
        y1 += u * w2[h * 2 + 1];
    }
    float r = (y0 * iT2) * sigf(y1 * iT2);
    g_at[(size_t)b * DMx + d * Mx + slot] = r;
}

// ---------------- synchrony ----------------
__global__ void k_synch(int base, float* __restrict__ out) {
    __shared__ float S[Mx * NSYx];
    int b = blockIdx.x, tid = threadIdx.x;
    for (int t = tid; t < Mx * NSYx; t += 256) {
        int mp = t & 31, j = t >> 5;
        float val = g_at[(size_t)b * DMx + (Dx - NSYx + j) * Mx + mp];
        int ml = (mp - base + 32) & 31;
        S[ml * NSYx + j] = val;
    }
    __syncthreads();
    for (int s = tid; s < SYNCHx; s += 256) {
        int ti = g_tri_i[s], tj = g_tri_j[s];
        float acc = 0.0f;
#pragma unroll
        for (int m = 0; m < Mx; m++)
            acc += g_decay[m * SYNCHx + s] * S[m * NSYx + ti] * S[m * NSYx + tj];
        out[(size_t)b * SYNCHx + s] = acc * g_invden[s];
    }
}

// ---------------- final un-ring copy ----------------
__global__ void k_final(float* __restrict__ out) {
    int idx = blockIdx.x * blockDim.x + threadIdx.x;
    if (idx >= BDMx) return;
    int m = idx & 31;
    int src = (idx & ~31) | ((m + ITERSx) & 31);
    out[idx] = g_st[src];
    out[BDMx + idx] = g_at[src];
}

// =====================================================================
extern "C" void kernel_launch(void* const* d_in, const int* in_sizes, int n_in,
                              void* d_out, int out_size) {
    (void)in_sizes; (void)n_in; (void)out_size;
    const float* obs      = (const float*)d_in[0];
    const unsigned char* dones_raw = (const unsigned char*)d_in[1];
    const float* st_in    = (const float*)d_in[3];
    const float* at_in    = (const float*)d_in[4];
    const float* start_st = (const float*)d_in[5];
    const float* start_at = (const float*)d_in[6];
    const float* bb_w1    = (const float*)d_in[7];
    const float* bb_b1    = (const float*)d_in[8];
    const float* ln1s     = (const float*)d_in[9];
    const float* ln1b     = (const float*)d_in[10];
    const float* bb_w2    = (const float*)d_in[11];
    const float* bb_b2    = (const float*)d_in[12];
    const float* ln2s     = (const float*)d_in[13];
    const float* ln2b     = (const float*)d_in[14];
    const float* syn_w1   = (const float*)d_in[15];
    const float* syn_b1   = (const float*)d_in[16];
    const float* sln1s    = (const float*)d_in[17];
    const float* sln1b    = (const float*)d_in[18];
    const float* syn_w2   = (const float*)d_in[19];
    const float* syn_b2   = (const float*)d_in[20];
    const float* sln2s    = (const float*)d_in[21];
    const float* sln2b    = (const float*)d_in[22];
    const float* nlm1_w   = (const float*)d_in[23];
    const float* nlm1_b   = (const float*)d_in[24];
    const float* nlm1_T   = (const float*)d_in[25];
    const float* nlm2_w   = (const float*)d_in[26];
    const float* nlm2_b   = (const float*)d_in[27];
    const float* nlm2_T   = (const float*)d_in[28];
    const float* decay_p  = (const float*)d_in[29];
    float* out = (float*)d_out;

    void *p_st, *p_y;
    void *p_obshi, *p_obslo, *p_fhi, *p_flo, *p_prehi, *p_prelo, *p_h1hi, *p_h1lo;
    void *p_wb1h, *p_wb1l, *p_wb2h, *p_wb2l, *p_ws1h, *p_ws1l, *p_ws2h, *p_ws2l;
    cudaGetSymbolAddress(&p_st, g_st);
    cudaGetSymbolAddress(&p_y, g_y);
    cudaGetSymbolAddress(&p_obshi, g_obshi);  cudaGetSymbolAddress(&p_obslo, g_obslo);
    cudaGetSymbolAddress(&p_fhi, g_fhi);      cudaGetSymbolAddress(&p_flo, g_flo);
    cudaGetSymbolAddress(&p_prehi, g_prehi);  cudaGetSymbolAddress(&p_prelo, g_prelo);
    cudaGetSymbolAddress(&p_h1hi, g_h1hi);    cudaGetSymbolAddress(&p_h1lo, g_h1lo);
    cudaGetSymbolAddress(&p_wb1h, g_wb1hi);   cudaGetSymbolAddress(&p_wb1l, g_wb1lo);
    cudaGetSymbolAddress(&p_wb2h, g_wb2hi);   cudaGetSymbolAddress(&p_wb2l, g_wb2lo);
    cudaGetSymbolAddress(&p_ws1h, g_ws1hi);   cudaGetSymbolAddress(&p_ws1l, g_ws1lo);
    cudaGetSymbolAddress(&p_ws2h, g_ws2hi);   cudaGetSymbolAddress(&p_ws2l, g_ws2lo);
    float* gst = (float*)p_st;
    float* gy  = (float*)p_y;

    static int smem_set = 0;
    int gsmem = 2 * GBUF_BYTES + 1024;
    if (!smem_set) {
        cudaFuncSetAttribute(k_tgemm, cudaFuncAttributeMaxDynamicSharedMemorySize, gsmem);
        smem_set = 1;
    }

    // prep
    k_dones<<<1, 256>>>(dones_raw);
    k_decay<<<(SYNCHx + 255) / 256, 256>>>(decay_p);
    k_init<<<BDMx / 256, 256>>>(st_in, at_in, start_st, start_at);
    k_wt<<<(Dx * 1024 + 255) / 256, 256>>>(nlm1_w, nlm2_w);
    k_split_obs<<<(Bx * OBSx) / 256, 256>>>(obs);
    k_tsplit<<<dim3(256 / 32, 1024 / 32), 256>>>(bb_w1, 256, 1024,
        (__nv_bfloat16*)p_wb1h, (__nv_bfloat16*)p_wb1l);
    k_tsplit<<<dim3(512 / 32, 1024 / 32), 256>>>(bb_w2, 512, 1024,
        (__nv_bfloat16*)p_wb2h, (__nv_bfloat16*)p_wb2l);
    k_tsplit<<<dim3(1536 / 32, 2048 / 32), 256>>>(syn_w1, 1536, 2048,
        (__nv_bfloat16*)p_ws1h, (__nv_bfloat16*)p_ws1l);
    k_tsplit<<<dim3(1024 / 32, 2048 / 32), 256>>>(syn_w2, 1024, 2048,
        (__nv_bfloat16*)p_ws2h, (__nv_bfloat16*)p_ws2l);

    // backbone
    k_tgemm<<<dim3(1024 / 64, Bx / 64), 256, gsmem>>>(
        (const __nv_bfloat16*)p_obshi, (const __nv_bfloat16*)p_obslo,
        (const __nv_bfloat16*)p_wb1h, (const __nv_bfloat16*)p_wb1l,
        bb_b1, gy, 256, 1024);
    k_glu_ln<<<Bx, 256>>>(gy, DINx, ln1s, ln1b, nullptr, 0, 0,
        (__nv_bfloat16*)p_fhi, (__nv_bfloat16*)p_flo);
    k_tgemm<<<dim3(1024 / 64, Bx / 64), 256, gsmem>>>(
        (const __nv_bfloat16*)p_fhi, (const __nv_bfloat16*)p_flo,
        (const __nv_bfloat16*)p_wb2h, (const __nv_bfloat16*)p_wb2l,
        bb_b2, gy, 512, 1024);
    k_glu_ln<<<Bx, 256>>>(gy, DINx, ln2s, ln2b, nullptr, 0, 0,
        (__nv_bfloat16*)p_fhi, (__nv_bfloat16*)p_flo);

    for (int i = 0; i < ITERSx; i++) {
        int physlast = (Mx - 1 + i) & 31;
        k_gather<<<(Bx * (DINx + Dx)) / 256, 256>>>(physlast);
        k_tgemm<<<dim3(2048 / 64, Bx / 64), 256, gsmem>>>(
            (const __nv_bfloat16*)p_prehi, (const __nv_bfloat16*)p_prelo,
            (const __nv_bfloat16*)p_ws1h, (const __nv_bfloat16*)p_ws1l,
            syn_b1, gy, 1536, 2048);
        k_glu_ln<<<Bx, 256>>>(gy, Dx, sln1s, sln1b, nullptr, 0, 0,
            (__nv_bfloat16*)p_h1hi, (__nv_bfloat16*)p_h1lo);
        k_tgemm<<<dim3(2048 / 64, Bx / 64), 256, gsmem>>>(
            (const __nv_bfloat16*)p_h1hi, (const __nv_bfloat16*)p_h1lo,
            (const __nv_bfloat16*)p_ws2h, (const __nv_bfloat16*)p_ws2l,
            syn_b2, gy, 1024, 2048);
        k_glu_ln<<<Bx, 256>>>(gy, Dx, sln2s, sln2b, gst + i, DMx, Mx, nullptr, nullptr);
        k_nlm<<<Dx, 256>>>(i + 1, i, nlm1_b, nlm1_T, nlm2_b, nlm2_T);
        if (i == ITERSx - 1)
            k_synch<<<Bx, 256>>>(ITERSx, out + 2 * (size_t)BDMx);
    }
    k_final<<<BDMx / 256, 256>>>(out);
}

// round 4
// speedup vs baseline: 2.5691x; 1.2020x over previous
#include <cuda_runtime.h>
#include <cuda_bf16.h>
#include <math.h>
#include <stdint.h>

#define Bx    256
#define OBSx  256
#define DINx  512
#define Dx    1024
#define Mx    32
#define HIDx  16
#define NSYx  64
#define ITERSx 4
#define SYNCHx 2080
#define DMx   (Dx * Mx)          // 32768
#define BDx   (Bx * Dx)          // 262144
#define BDMx  (Bx * Dx * Mx)     // 8388608

// ---------------- scratch (static device globals, no allocation) ----------------
__device__ float g_y[Bx * 2 * Dx];
__device__ __align__(16) float g_w1t[Dx * 1024];     // [d][m*32+h] (NLM)
__device__ float g_w2t[Dx * 32];                     // [d][h*2+c]  (NLM)
__device__ float g_decay[Mx * SYNCHx];
__device__ float g_invden[SYNCHx];
__device__ int   g_tri_i[SYNCHx];
__device__ int   g_tri_j[SYNCHx];
__device__ int   g_dones[Bx];
__device__ __align__(16) float g_hst[ITERSx][BDx];   // [i][b*1024+d]
__device__ __align__(16) float g_hat[ITERSx][BDx];   // [i][d*256+b]

// bf16 hi/lo split buffers
__device__ __align__(256) __nv_bfloat16 g_obshi[Bx * OBSx];
__device__ __align__(256) __nv_bfloat16 g_obslo[Bx * OBSx];
__device__ __align__(256) __nv_bfloat16 g_prehi[Bx * (DINx + Dx)];  // [b][1536]
__device__ __align__(256) __nv_bfloat16 g_prelo[Bx * (DINx + Dx)];
__device__ __align__(256) __nv_bfloat16 g_h1hi[Bx * Dx];
__device__ __align__(256) __nv_bfloat16 g_h1lo[Bx * Dx];
// weights transposed to [N][K] bf16 hi/lo
__device__ __align__(256) __nv_bfloat16 g_wb1hi[1024 * 256];
__device__ __align__(256) __nv_bfloat16 g_wb1lo[1024 * 256];
__device__ __align__(256) __nv_bfloat16 g_wb2hi[1024 * 512];
__device__ __align__(256) __nv_bfloat16 g_wb2lo[1024 * 512];
__device__ __align__(256) __nv_bfloat16 g_ws1hi[2048 * 1536];
__device__ __align__(256) __nv_bfloat16 g_ws1lo[2048 * 1536];
__device__ __align__(256) __nv_bfloat16 g_ws2hi[2048 * 1024];
__device__ __align__(256) __nv_bfloat16 g_ws2lo[2048 * 1024];

__device__ __forceinline__ float sigf(float x) {
    return __fdividef(1.0f, 1.0f + __expf(-x));
}

__device__ __forceinline__ void split2(float v, __nv_bfloat16* h, __nv_bfloat16* l) {
    __nv_bfloat16 hh = __float2bfloat16(v);
    *h = hh;
    *l = __float2bfloat16(v - __bfloat162float(hh));
}

// ================= PTX helpers (portable sm_80+ subset) =================
__device__ __forceinline__ uint32_t smem_u32(const void* p) {
    uint32_t a;
    asm("{ .reg .u64 t; cvta.to.shared.u64 t, %1; cvt.u32.u64 %0, t; }" : "=r"(a) : "l"(p));
    return a;
}

#define SW128(off) ((off) ^ (((off) >> 3) & 0x70))

#define CP_ASYNC16(dst, src) \
    asm volatile("cp.async.cg.shared.global [%0], [%1], 16;" :: "r"(dst), "l"(src))
#define CP_COMMIT()  asm volatile("cp.async.commit_group;" ::: "memory")
#define CP_WAIT(n)   asm volatile("cp.async.wait_group %0;" :: "n"(n) : "memory")

#define LDSM4(r, addr) \
    asm volatile("ldmatrix.sync.aligned.m8n8.x4.shared.b16 {%0,%1,%2,%3}, [%4];" \
        : "=r"((r)[0]), "=r"((r)[1]), "=r"((r)[2]), "=r"((r)[3]) : "r"(addr))

#define MMA16816(acc, a, b0, b1) \
    asm volatile("mma.sync.aligned.m16n8k16.row.col.f32.bf16.bf16.f32 " \
        "{%0,%1,%2,%3}, {%4,%5,%6,%7}, {%8,%9}, {%0,%1,%2,%3};" \
        : "+f"((acc)[0]), "+f"((acc)[1]), "+f"((acc)[2]), "+f"((acc)[3]) \
        : "r"((a)[0]), "r"((a)[1]), "r"((a)[2]), "r"((a)[3]), "r"(b0), "r"(b1))

// ================= split-bf16 HMMA GEMM =================
// C[Mr,N] = (Ahi+Alo)[Mr,K](row stride lda) @ ((Bhi+Blo)[N,K])^T + bias.
// CTA tile 64x64, BK=64, 8 warps, each warp 32m x 16n. Double-buffered cp.async.
#define GBUF_BYTES 32768
__global__ void __launch_bounds__(256) k_tgemm(
    const __nv_bfloat16* __restrict__ Ahi, const __nv_bfloat16* __restrict__ Alo,
    const __nv_bfloat16* __restrict__ Bhi, const __nv_bfloat16* __restrict__ Blo,
    const float* __restrict__ bias, float* __restrict__ C, int K, int lda, int N)
{
    extern __shared__ char smem_raw[];
    uint32_t sbase = smem_u32(smem_raw);
    uint32_t abase = (sbase + 1023u) & ~1023u;

    int tid = threadIdx.x;
    int lane = tid & 31;
    int wid = tid >> 5;
    int warp_m = wid & 1;
    int warp_n = wid >> 1;
    int row0 = blockIdx.y * 64;
    int col0 = blockIdx.x * 64;
    int NC = K >> 6;

    float acc[2][2][4];
#pragma unroll
    for (int i = 0; i < 2; i++)
#pragma unroll
        for (int j = 0; j < 2; j++)
#pragma unroll
            for (int q = 0; q < 4; q++) acc[i][j][q] = 0.0f;

    auto load_chunk = [&](int buf, int k0) {
        uint32_t bb = abase + buf * GBUF_BYTES;
#pragma unroll
        for (int i = 0; i < 2; i++) {
            int u = tid + i * 256;
            int r = u >> 3, ch = u & 7;
            uint32_t soff = SW128((uint32_t)(r * 128 + ch * 16));
            size_t goA = (size_t)(row0 + r) * lda + k0 + ch * 8;
            size_t goB = (size_t)(col0 + r) * K + k0 + ch * 8;
            CP_ASYNC16(bb + soff,          Ahi + goA);
            CP_ASYNC16(bb + 8192 + soff,   Alo + goA);
            CP_ASYNC16(bb + 16384 + soff,  Bhi + goB);
            CP_ASYNC16(bb + 24576 + soff,  Blo + goB);
        }
    };

    load_chunk(0, 0);
    CP_COMMIT();

    int a_r = warp_m * 32 + (lane & 15);
    int a_csel = (lane >> 4) << 3;
    int b_r = warp_n * 16 + (lane & 7) + ((lane >> 4) << 3);
    int b_csel = ((lane >> 3) & 1) << 3;

    for (int c = 0; c < NC; c++) {
        if (c + 1 < NC) { load_chunk((c + 1) & 1, (c + 1) * 64); CP_COMMIT(); CP_WAIT(1); }
        else            { CP_WAIT(0); }
        __syncthreads();

        uint32_t bb = abase + (c & 1) * GBUF_BYTES;
#pragma unroll
        for (int kk = 0; kk < 4; kk++) {
            int k0 = kk * 16;
            uint32_t ah[2][4], al[2][4], bh[4], bl[4];
#pragma unroll
            for (int mf = 0; mf < 2; mf++) {
                uint32_t off = SW128((uint32_t)((a_r + mf * 16) * 128 + (k0 + a_csel) * 2));
                LDSM4(ah[mf], bb + off);
                LDSM4(al[mf], bb + 8192 + off);
            }
            {
                uint32_t off = SW128((uint32_t)(b_r * 128 + (k0 + b_csel) * 2));
                LDSM4(bh, bb + 16384 + off);
                LDSM4(bl, bb + 24576 + off);
            }
#pragma unroll
            for (int mf = 0; mf < 2; mf++) {
#pragma unroll
                for (int nf = 0; nf < 2; nf++) {
                    MMA16816(acc[mf][nf], ah[mf], bh[2 * nf], bh[2 * nf + 1]);
                    MMA16816(acc[mf][nf], ah[mf], bl[2 * nf], bl[2 * nf + 1]);
                    MMA16816(acc[mf][nf], al[mf], bh[2 * nf], bh[2 * nf + 1]);
                }
            }
        }
        __syncthreads();
    }

    int gid = lane >> 2, tig = lane & 3;
#pragma unroll
    for (int mf = 0; mf < 2; mf++) {
#pragma unroll
        for (int nf = 0; nf < 2; nf++) {
            int r = row0 + warp_m * 32 + mf * 16 + gid;
            int cc = col0 + warp_n * 16 + nf * 8 + tig * 2;
            float2 b01 = *(const float2*)&bias[cc];
            float2 o0 = { acc[mf][nf][0] + b01.x, acc[mf][nf][1] + b01.y };
            float2 o1 = { acc[mf][nf][2] + b01.x, acc[mf][nf][3] + b01.y };
            *(float2*)&C[(size_t)r * N + cc] = o0;
            *(float2*)&C[(size_t)(r + 8) * N + cc] = o1;
        }
    }
}

// ================= mega prep kernel =================
// block ranges: [0]=dones, [1,10)=decay, [10,266)=obs split, [266,4362)=nlm wt,
// [4362,4618)=tsplit bb_w1, [4618,5130)=bb_w2, [5130,8202)=syn_w1, [8202,10250)=syn_w2
__device__ void tsplit_block(const float* __restrict__ W, int K, int N,
                             __nv_bfloat16* __restrict__ Ohi, __nv_bfloat16* __restrict__ Olo,
                             int local) {
    __shared__ float t[32][33];
    int ktiles = K >> 5;
    int kt = local % ktiles, nt = local / ktiles;
    int k0 = kt * 32, n0 = nt * 32;
    int tx = threadIdx.x & 31, ty = threadIdx.x >> 5;
    for (int i = ty; i < 32; i += 8)
        t[i][tx] = W[(size_t)(k0 + i) * N + n0 + tx];
    __syncthreads();
    for (int i = ty; i < 32; i += 8) {
        float v = t[tx][i];
        size_t o = (size_t)(n0 + i) * K + k0 + tx;
        __nv_bfloat16 h, l;
        split2(v, &h, &l);
        Ohi[o] = h; Olo[o] = l;
    }
}

__global__ void k_prep(const unsigned char* __restrict__ dones_raw,
                       const float* __restrict__ dp,
                       const float* __restrict__ obs,
                       const float* __restrict__ nw1, const float* __restrict__ nw2,
                       const float* __restrict__ bw1, const float* __restrict__ bw2,
                       const float* __restrict__ sw1, const float* __restrict__ sw2) {
    int bid = blockIdx.x, tid = threadIdx.x;
    if (bid == 0) {
        __shared__ int mode;
        if (tid == 0) {
            bool nzoff = false, floatlike = true, anynz = false;
            for (int i = 0; i < Bx; i++) {
                unsigned char v = dones_raw[i];
                if (v) {
                    anynz = true;
                    int r = i & 3;
                    if (r != 0) nzoff = true;
                    bool okf = (r == 2 && v == 0x80) || (r == 3 && v == 0x3F);
                    if (!okf) floatlike = false;
                }
            }
            mode = (nzoff && floatlike && anynz) ? 2 : (nzoff ? 0 : 1);
        }
        __syncthreads();
        int b = tid, m = mode, v;
        if (m == 0)      v = (dones_raw[b] != 0);
        else if (m == 1) v = (((const int*)dones_raw)[b] != 0);
        else             v = (((const float*)dones_raw)[b] != 0.0f);
        g_dones[b] = v;
    } else if (bid < 10) {
        int s = (bid - 1) * 256 + tid;
        if (s < SYNCHx) {
            float c = fminf(fmaxf(dp[s], 0.0f), 4.0f);
            float sum = 0.0f;
            for (int m = 0; m < Mx; m++) {
                float v = __expf(-(float)(Mx - 1 - m) * c);
                g_decay[m * SYNCHx + s] = v;
                sum += v;
            }
            g_invden[s] = rsqrtf(sum);
            int i = 0, base = 0;
            while (s >= base + (NSYx - i)) { base += NSYx - i; i++; }
            g_tri_i[s] = i;
            g_tri_j[s] = i + (s - base);
        }
    } else if (bid < 266) {
        int i = (bid - 10) * 256 + tid;
        split2(obs[i], &g_obshi[i], &g_obslo[i]);
    } else if (bid < 4362) {
        int idx = (bid - 266) * 256 + tid;
        int d = idx >> 10, mh = idx & 1023;
        g_w1t[idx] = nw1[mh * Dx + d];
        if (idx < Dx * 32) {
            int d2 = idx >> 5, hc = idx & 31;
            g_w2t[idx] = nw2[hc * Dx + d2];
        }
    } else if (bid < 4618) {
        tsplit_block(bw1, 256, 1024, g_wb1hi, g_wb1lo, bid - 4362);
    } else if (bid < 5130) {
        tsplit_block(bw2, 512, 1024, g_wb2hi, g_wb2lo, bid - 4618);
    } else if (bid < 8202) {
        tsplit_block(sw1, 1536, 2048, g_ws1hi, g_ws1lo, bid - 5130);
    } else {
        tsplit_block(sw2, 1024, 2048, g_ws2hi, g_ws2lo, bid - 8202);
    }
}

// ================= GLU + LN -> bf16 split (optional at-gather for iter 0) ===
__global__ void k_gluln_split(const float* __restrict__ y, int halfN,
                              const float* __restrict__ sc, const float* __restrict__ bi,
                              __nv_bfloat16* __restrict__ ohi, __nv_bfloat16* __restrict__ olo,
                              int ostride, int gather,
                              const float* __restrict__ at_in,
                              const float* __restrict__ start_at) {
    __shared__ float v[1024];
    __shared__ float red_s[8], red_q[8];
    int row = blockIdx.x, tid = threadIdx.x;
    const float* yr = y + (size_t)row * 2 * halfN;
    float sum = 0.0f, sq = 0.0f;
    for (int c = tid; c < halfN; c += 256) {
        float a = yr[c];
        float g = yr[halfN + c];
        float val = a * sigf(g);
        v[c] = val;
        sum += val;
        sq += val * val;
    }
#pragma unroll
    for (int o = 16; o > 0; o >>= 1) {
        sum += __shfl_xor_sync(0xffffffffu, sum, o);
        sq  += __shfl_xor_sync(0xffffffffu, sq, o);
    }
    int w = tid >> 5;
    if ((tid & 31) == 0) { red_s[w] = sum; red_q[w] = sq; }
    __syncthreads();
    if (tid == 0) {
        float ts = 0.0f, tq = 0.0f;
        for (int i = 0; i < 8; i++) { ts += red_s[i]; tq += red_q[i]; }
        red_s[0] = ts; red_q[0] = tq;
    }
    __syncthreads();
    float invN = 1.0f / (float)halfN;
    float mean = red_s[0] * invN;
    float var = red_q[0] * invN - mean * mean;
    float inv = rsqrtf(var + 1e-6f);
    for (int c = tid; c < halfN; c += 256) {
        float val = (v[c] - mean) * inv * sc[c] + bi[c];
        size_t o = (size_t)row * ostride + c;
        split2(val, &ohi[o], &olo[o]);
    }
    if (gather) {
        bool done = g_dones[row] != 0;
        for (int c = tid; c < Dx; c += 256) {
            float val = done ? start_at[c * 32 + 31]
                             : at_in[((size_t)(row * Dx + c)) * 32 + 31];
            size_t o = (size_t)row * ostride + halfN + c;
            split2(val, &ohi[o], &olo[o]);
        }
    }
}

// GLU + LN -> fp32 contiguous (h_st[i])
__global__ void k_gluln_f32(const float* __restrict__ y, int halfN,
                            const float* __restrict__ sc, const float* __restrict__ bi,
                            float* __restrict__ out) {
    __shared__ float v[1024];
    __shared__ float red_s[8], red_q[8];
    int row = blockIdx.x, tid = threadIdx.x;
    const float* yr = y + (size_t)row * 2 * halfN;
    float sum = 0.0f, sq = 0.0f;
    for (int c = tid; c < halfN; c += 256) {
        float a = yr[c];
        float g = yr[halfN + c];
        float val = a * sigf(g);
        v[c] = val;
        sum += val;
        sq += val * val;
    }
#pragma unroll
    for (int o = 16; o > 0; o >>= 1) {
        sum += __shfl_xor_sync(0xffffffffu, sum, o);
        sq  += __shfl_xor_sync(0xffffffffu, sq, o);
    }
    int w = tid >> 5;
    if ((tid & 31) == 0) { red_s[w] = sum; red_q[w] = sq; }
    __syncthreads();
    if (tid == 0) {
        float ts = 0.0f, tq = 0.0f;
        for (int i = 0; i < 8; i++) { ts += red_s[i]; tq += red_q[i]; }
        red_s[0] = ts; red_q[0] = tq;
    }
    __syncthreads();
    float invN = 1.0f / (float)halfN;
    float mean = red_s[0] * invN;
    float var = red_q[0] * invN - mean * mean;
    float inv = rsqrtf(var + 1e-6f);
    for (int c = tid; c < halfN; c += 256)
        out[(size_t)row * halfN + c] = (v[c] - mean) * inv * sc[c] + bi[c];
}

// ================= NLM (templated on iteration) =================
// block = 8 warps, warp w -> d = d0+w; lanes = 32 b per chunk, 8 chunks.
template<int IT>
__global__ void __launch_bounds__(256) k_nlm(
    const float* __restrict__ st_in, const float* __restrict__ start_st,
    const float* __restrict__ b1, const float* __restrict__ T1,
    const float* __restrict__ b2, const float* __restrict__ T2) {
    __shared__ float4 w1v[8][256];
    __shared__ float w2s[8][32], b1s[8][32], b2s[8][2];
    __shared__ float hsm[IT + 1][32][9];
    __shared__ float xsm[32][9];
    __shared__ float invT[2];
    int tid = threadIdx.x;
    int w = tid >> 5, lane = tid & 31;
    int d0 = blockIdx.x * 8;
    for (int u = tid; u < 2048; u += 256) {
        int dl = u >> 8, q = u & 255;
        w1v[dl][q] = ((const float4*)g_w1t)[(size_t)(d0 + dl) * 256 + q];
    }
    {
        int dl = w, h = lane;
        w2s[dl][h] = g_w2t[(d0 + dl) * 32 + h];
        b1s[dl][h] = b1[(d0 + dl) * 32 + h];
    }
    if (tid < 16) b2s[tid >> 1][tid & 1] = b2[(d0 + (tid >> 1)) * 2 + (tid & 1)];
    if (tid == 0) { invT[0] = 1.0f / T1[0]; invT[1] = 1.0f / T2[0]; }
    __syncthreads();
    float iT1 = invT[0], iT2 = invT[1];
    int d = d0 + w;

    for (int ch = 0; ch < 8; ch++) {
        if (tid < (IT + 1) * 64) {
            int j = tid >> 6, rem = tid & 63, bl = rem >> 1, hf = rem & 1;
            float4 hv = *(const float4*)&g_hst[j][(size_t)(ch * 32 + bl) * Dx + d0 + hf * 4];
            hsm[j][bl][hf * 4 + 0] = hv.x;
            hsm[j][bl][hf * 4 + 1] = hv.y;
            hsm[j][bl][hf * 4 + 2] = hv.z;
            hsm[j][bl][hf * 4 + 3] = hv.w;
        }
        __syncthreads();
        int b = ch * 32 + lane;
        const float* stp = g_dones[b] ? (start_st + d * 32)
                                      : (st_in + ((size_t)(b << 10) + d) * 32);
        float sin[32];
#pragma unroll
        for (int q = 0; q < 8; q++) {
            float4 t4 = ((const float4*)stp)[q];
            sin[q * 4 + 0] = t4.x; sin[q * 4 + 1] = t4.y;
            sin[q * 4 + 2] = t4.z; sin[q * 4 + 3] = t4.w;
        }
        float hreg[IT + 1];
#pragma unroll
        for (int j = 0; j <= IT; j++) hreg[j] = hsm[j][lane][w];

        float x[32];
#pragma unroll
        for (int h = 0; h < 32; h++) x[h] = b1s[w][h];
#pragma unroll
        for (int m = 0; m < 32; m++) {
            float a = (m < 31 - IT) ? sin[m + IT + 1] : hreg[m - (31 - IT)];
#pragma unroll
            for (int q = 0; q < 8; q++) {
                float4 wv = w1v[w][m * 8 + q];
                x[q * 4 + 0] += a * wv.x;
                x[q * 4 + 1] += a * wv.y;
                x[q * 4 + 2] += a * wv.z;
                x[q * 4 + 3] += a * wv.w;
            }
        }
        float y0 = b2s[w][0], y1 = b2s[w][1];
#pragma unroll
        for (int h = 0; h < 16; h++) {
            float u = (x[h] * iT1) * sigf(x[h + 16] * iT1);
            y0 += u * w2s[w][h * 2 + 0];
            y1 += u * w2s[w][h * 2 + 1];
        }
        float r = (y0 * iT2) * sigf(y1 * iT2);
        g_hat[IT][(size_t)d * Bx + b] = r;
        if (IT < 3) {
            xsm[lane][w] = r;
            __syncthreads();
            int bl = tid >> 3, dl = tid & 7;
            float vv = xsm[bl][dl];
            __nv_bfloat16 hh, ll;
            split2(vv, &hh, &ll);
            size_t o = (size_t)(ch * 32 + bl) * (DINx + Dx) + DINx + d0 + dl;
            g_prehi[o] = hh; g_prelo[o] = ll;
        }
        __syncthreads();
    }
}

// ================= final assembly + synchrony (one launch) =================
__global__ void k_fin(float* __restrict__ out,
                      const float* __restrict__ st_in, const float* __restrict__ at_in,
                      const float* __restrict__ start_st, const float* __restrict__ start_at) {
    int tid = threadIdx.x;
    if (blockIdx.x < 1024) {
        // assembly: tile = 8 d x 32 b
        __shared__ float hsm[4][32][9];
        int local = blockIdx.x;
        int dt = local & 127, bt = local >> 7;
        int d0 = dt * 8, b0 = bt * 32;
        {
            int j = tid >> 6, rem = tid & 63, bl = rem >> 1, hf = rem & 1;
            float4 hv = *(const float4*)&g_hst[j][(size_t)(b0 + bl) * Dx + d0 + hf * 4];
            hsm[j][bl][hf * 4 + 0] = hv.x;
            hsm[j][bl][hf * 4 + 1] = hv.y;
            hsm[j][bl][hf * 4 + 2] = hv.z;
            hsm[j][bl][hf * 4 + 3] = hv.w;
        }
        __syncthreads();
        int w = tid >> 5, lane = tid & 31;
        int d = d0 + w, b = b0 + lane;
        bool done = g_dones[b] != 0;
        const float* stp = done ? (start_st + d * 32) : (st_in + ((size_t)(b << 10) + d) * 32);
        const float* atp = done ? (start_at + d * 32) : (at_in + ((size_t)(b << 10) + d) * 32);
        float so[32], ao[32];
#pragma unroll
        for (int q = 1; q < 8; q++) {
            float4 t4 = ((const float4*)stp)[q];
            so[q * 4 - 4] = t4.x; so[q * 4 - 3] = t4.y; so[q * 4 - 2] = t4.z; so[q * 4 - 1] = t4.w;
            float4 u4 = ((const float4*)atp)[q];
            ao[q * 4 - 4] = u4.x; ao[q * 4 - 3] = u4.y; ao[q * 4 - 2] = u4.z; ao[q * 4 - 1] = u4.w;
        }
#pragma unroll
        for (int j = 0; j < 4; j++) {
            so[28 + j] = hsm[j][lane][w];
            ao[28 + j] = g_hat[j][(size_t)d * Bx + b];
        }
        float* o1 = out + ((size_t)(b << 10) + d) * 32;
        float* o2 = o1 + BDMx;
#pragma unroll
        for (int q = 0; q < 8; q++) {
            float4 v1 = { so[q * 4], so[q * 4 + 1], so[q * 4 + 2], so[q * 4 + 3] };
            float4 v2 = { ao[q * 4], ao[q * 4 + 1], ao[q * 4 + 2], ao[q * 4 + 3] };
            ((float4*)o1)[q] = v1;
            ((float4*)o2)[q] = v2;
        }
    } else {
        // synchrony
        __shared__ float S[Mx * NSYx];   // [m][j]
        int b = blockIdx.x - 1024;
        bool done = g_dones[b] != 0;
        float* outs = out + 2 * (size_t)BDMx;
        for (int t = tid; t < Mx * NSYx; t += 256) {
            int m = t & 31, j = t >> 5;
            int dd = Dx - NSYx + j;
            float val;
            if (m < 28)
                val = done ? start_at[dd * 32 + m + 4]
                           : at_in[((size_t)(b * Dx + dd)) * 32 + m + 4];
            else
                val = g_hat[m - 28][(size_t)dd * Bx + b];
            S[m * NSYx + j] = val;
        }
        __syncthreads();
        for (int s = tid; s < SYNCHx; s += 256) {
            int ti = g_tri_i[s], tj = g_tri_j[s];
            float acc = 0.0f;
#pragma unroll
            for (int m = 0; m < Mx; m++)
                acc += g_decay[m * SYNCHx + s] * S[m * NSYx + ti] * S[m * NSYx + tj];
            outs[(size_t)b * SYNCHx + s] = acc * g_invden[s];
        }
    }
}

// =====================================================================
extern "C" void kernel_launch(void* const* d_in, const int* in_sizes, int n_in,
                              void* d_out, int out_size) {
    (void)in_sizes; (void)n_in; (void)out_size;
    const float* obs      = (const float*)d_in[0];
    const unsigned char* dones_raw = (const unsigned char*)d_in[1];
    const float* st_in    = (const float*)d_in[3];
    const float* at_in    = (const float*)d_in[4];
    const float* start_st = (const float*)d_in[5];
    const float* start_at = (const float*)d_in[6];
    const float* bb_w1    = (const float*)d_in[7];
    const float* bb_b1    = (const float*)d_in[8];
    const float* ln1s     = (const float*)d_in[9];
    const float* ln1b     = (const float*)d_in[10];
    const float* bb_w2    = (const float*)d_in[11];
    const float* bb_b2    = (const float*)d_in[12];
    const float* ln2s     = (const float*)d_in[13];
    const float* ln2b     = (const float*)d_in[14];
    const float* syn_w1   = (const float*)d_in[15];
    const float* syn_b1   = (const float*)d_in[16];
    const float* sln1s    = (const float*)d_in[17];
    const float* sln1b    = (const float*)d_in[18];
    const float* syn_w2   = (const float*)d_in[19];
    const float* syn_b2   = (const float*)d_in[20];
    const float* sln2s    = (const float*)d_in[21];
    const float* sln2b    = (const float*)d_in[22];
    const float* nlm1_w   = (const float*)d_in[23];
    const float* nlm1_b   = (const float*)d_in[24];
    const float* nlm1_T   = (const float*)d_in[25];
    const float* nlm2_w   = (const float*)d_in[26];
    const float* nlm2_b   = (const float*)d_in[27];
    const float* nlm2_T   = (const float*)d_in[28];
    const float* decay_p  = (const float*)d_in[29];
    float* out = (float*)d_out;

    void *p_y, *p_hst;
    void *p_obshi, *p_obslo, *p_prehi, *p_prelo, *p_h1hi, *p_h1lo;
    void *p_wb1h, *p_wb1l, *p_wb2h, *p_wb2l, *p_ws1h, *p_ws1l, *p_ws2h, *p_ws2l;
    cudaGetSymbolAddress(&p_y, g_y);
    cudaGetSymbolAddress(&p_hst, g_hst);
    cudaGetSymbolAddress(&p_obshi, g_obshi);  cudaGetSymbolAddress(&p_obslo, g_obslo);
    cudaGetSymbolAddress(&p_prehi, g_prehi);  cudaGetSymbolAddress(&p_prelo, g_prelo);
    cudaGetSymbolAddress(&p_h1hi, g_h1hi);    cudaGetSymbolAddress(&p_h1lo, g_h1lo);
    cudaGetSymbolAddress(&p_wb1h, g_wb1hi);   cudaGetSymbolAddress(&p_wb1l, g_wb1lo);
    cudaGetSymbolAddress(&p_wb2h, g_wb2hi);   cudaGetSymbolAddress(&p_wb2l, g_wb2lo);
    cudaGetSymbolAddress(&p_ws1h, g_ws1hi);   cudaGetSymbolAddress(&p_ws1l, g_ws1lo);
    cudaGetSymbolAddress(&p_ws2h, g_ws2hi);   cudaGetSymbolAddress(&p_ws2l, g_ws2lo);
    float* gy   = (float*)p_y;
    float* ghst = (float*)p_hst;

    static int smem_set = 0;
    int gsmem = 2 * GBUF_BYTES + 1024;
    if (!smem_set) {
        cudaFuncSetAttribute(k_tgemm, cudaFuncAttributeMaxDynamicSharedMemorySize, gsmem);
        smem_set = 1;
    }

    // prep (1 launch)
    k_prep<<<10250, 256>>>(dones_raw, decay_p, obs, nlm1_w, nlm2_w,
                           bb_w1, bb_w2, syn_w1, syn_w2);

    // backbone (4 launches); f1 reuses h1 buffers
    k_tgemm<<<dim3(16, 4), 256, gsmem>>>(
        (const __nv_bfloat16*)p_obshi, (const __nv_bfloat16*)p_obslo,
        (const __nv_bfloat16*)p_wb1h, (const __nv_bfloat16*)p_wb1l,
        bb_b1, gy, 256, 256, 1024);
    k_gluln_split<<<Bx, 256>>>(gy, 512, ln1s, ln1b,
        (__nv_bfloat16*)p_h1hi, (__nv_bfloat16*)p_h1lo, 512, 0, nullptr, nullptr);
    k_tgemm<<<dim3(16, 4), 256, gsmem>>>(
        (const __nv_bfloat16*)p_h1hi, (const __nv_bfloat16*)p_h1lo,
        (const __nv_bfloat16*)p_wb2h, (const __nv_bfloat16*)p_wb2l,
        bb_b2, gy, 512, 512, 1024);
    k_gluln_split<<<Bx, 256>>>(gy, 512, ln2s, ln2b,
        (__nv_bfloat16*)p_prehi, (__nv_bfloat16*)p_prelo, 1536, 1, at_in, start_at);

    for (int i = 0; i < ITERSx; i++) {
        k_tgemm<<<dim3(32, 4), 256, gsmem>>>(
            (const __nv_bfloat16*)p_prehi, (const __nv_bfloat16*)p_prelo,
            (const __nv_bfloat16*)p_ws1h, (const __nv_bfloat16*)p_ws1l,
            syn_b1, gy, 1536, 1536, 2048);
        k_gluln_split<<<Bx, 256>>>(gy, 1024, sln1s, sln1b,
            (__nv_bfloat16*)p_h1hi, (__nv_bfloat16*)p_h1lo, 1024, 0, nullptr, nullptr);
        k_tgemm<<<dim3(32, 4), 256, gsmem>>>(
            (const __nv_bfloat16*)p_h1hi, (const __nv_bfloat16*)p_h1lo,
            (const __nv_bfloat16*)p_ws2h, (const __nv_bfloat16*)p_ws2l,
            syn_b2, gy, 1024, 1024, 2048);
        k_gluln_f32<<<Bx, 256>>>(gy, 1024, sln2s, sln2b, ghst + (size_t)i * BDx);
        switch (i) {
            case 0: k_nlm<0><<<128, 256>>>(st_in, start_st, nlm1_b, nlm1_T, nlm2_b, nlm2_T); break;
            case 1: k_nlm<1><<<128, 256>>>(st_in, start_st, nlm1_b, nlm1_T, nlm2_b, nlm2_T); break;
            case 2: k_nlm<2><<<128, 256>>>(st_in, start_st, nlm1_b, nlm1_T, nlm2_b, nlm2_T); break;
            case 3: k_nlm<3><<<128, 256>>>(st_in, start_st, nlm1_b, nlm1_T, nlm2_b, nlm2_T); break;
        }
    }

    k_fin<<<1024 + Bx, 256>>>(out, st_in, at_in, start_st, start_at);
}

// round 5
// speedup vs baseline: 2.5860x; 1.0066x over previous
#include <cuda_runtime.h>
#include <cuda_bf16.h>
#include <math.h>
#include <stdint.h>

#define Bx    256
#define OBSx  256
#define DINx  512
#define Dx    1024
#define Mx    32
#define HIDx  16
#define NSYx  64
#define ITERSx 4
#define SYNCHx 2080
#define DMx   (Dx * Mx)          // 32768
#define BDx   (Bx * Dx)          // 262144
#define BDMx  (Bx * Dx * Mx)     // 8388608

// ---------------- scratch (static device globals, no allocation) ----------------
__device__ float g_y[Bx * 2 * Dx];
__device__ __align__(16) float g_w1t[Dx * 1024];     // [d][m*32+h] (NLM)
__device__ float g_w2t[Dx * 32];                     // [d][h*2+c]  (NLM)
__device__ float g_decay[Mx * SYNCHx];
__device__ float g_invden[SYNCHx];
__device__ int   g_tri_i[SYNCHx];
__device__ int   g_tri_j[SYNCHx];
__device__ int   g_dones[Bx];
__device__ __align__(16) float g_hst[ITERSx][BDx];   // [i][b*1024+d]
__device__ __align__(16) float g_hat[ITERSx][BDx];   // [i][d*256+b]

// bf16 hi/lo split buffers
__device__ __align__(256) __nv_bfloat16 g_obshi[Bx * OBSx];
__device__ __align__(256) __nv_bfloat16 g_obslo[Bx * OBSx];
__device__ __align__(256) __nv_bfloat16 g_prehi[Bx * (DINx + Dx)];  // [b][1536]
__device__ __align__(256) __nv_bfloat16 g_prelo[Bx * (DINx + Dx)];
__device__ __align__(256) __nv_bfloat16 g_h1hi[Bx * Dx];
__device__ __align__(256) __nv_bfloat16 g_h1lo[Bx * Dx];
// weights transposed to [N][K] bf16 hi/lo
__device__ __align__(256) __nv_bfloat16 g_wb1hi[1024 * 256];
__device__ __align__(256) __nv_bfloat16 g_wb1lo[1024 * 256];
__device__ __align__(256) __nv_bfloat16 g_wb2hi[1024 * 512];
__device__ __align__(256) __nv_bfloat16 g_wb2lo[1024 * 512];
__device__ __align__(256) __nv_bfloat16 g_ws1hi[2048 * 1536];
__device__ __align__(256) __nv_bfloat16 g_ws1lo[2048 * 1536];
__device__ __align__(256) __nv_bfloat16 g_ws2hi[2048 * 1024];
__device__ __align__(256) __nv_bfloat16 g_ws2lo[2048 * 1024];

__device__ __forceinline__ float sigf(float x) {
    return __fdividef(1.0f, 1.0f + __expf(-x));
}

__device__ __forceinline__ void split2(float v, __nv_bfloat16* h, __nv_bfloat16* l) {
    __nv_bfloat16 hh = __float2bfloat16(v);
    *h = hh;
    *l = __float2bfloat16(v - __bfloat162float(hh));
}

// ================= PTX helpers (portable sm_80+ subset) =================
__device__ __forceinline__ uint32_t smem_u32(const void* p) {
    uint32_t a;
    asm("{ .reg .u64 t; cvta.to.shared.u64 t, %1; cvt.u32.u64 %0, t; }" : "=r"(a) : "l"(p));
    return a;
}

#define SW128(off) ((off) ^ (((off) >> 3) & 0x70))

#define CP_ASYNC16(dst, src) \
    asm volatile("cp.async.cg.shared.global [%0], [%1], 16;" :: "r"(dst), "l"(src))
#define CP_COMMIT()  asm volatile("cp.async.commit_group;" ::: "memory")
#define CP_WAIT(n)   asm volatile("cp.async.wait_group %0;" :: "n"(n) : "memory")

#define LDSM4(r, addr) \
    asm volatile("ldmatrix.sync.aligned.m8n8.x4.shared.b16 {%0,%1,%2,%3}, [%4];" \
        : "=r"((r)[0]), "=r"((r)[1]), "=r"((r)[2]), "=r"((r)[3]) : "r"(addr))

#define MMA16816(acc, a, b0, b1) \
    asm volatile("mma.sync.aligned.m16n8k16.row.col.f32.bf16.bf16.f32 " \
        "{%0,%1,%2,%3}, {%4,%5,%6,%7}, {%8,%9}, {%0,%1,%2,%3};" \
        : "+f"((acc)[0]), "+f"((acc)[1]), "+f"((acc)[2]), "+f"((acc)[3]) \
        : "r"((a)[0]), "r"((a)[1]), "r"((a)[2]), "r"((a)[3]), "r"(b0), "r"(b1))

// ================= split-bf16 HMMA GEMM, 3-stage pipeline =================
// C[Mr,N] = (Ahi+Alo)[Mr,K](row stride lda) @ ((Bhi+Blo)[N,K])^T + bias.
// CTA tile 64x64, BK=64, 8 warps, each warp 32m x 16n.
// 3-stage cp.async pipeline, ONE __syncthreads per K-chunk.
#define GBUF_BYTES 32768
#define GSTAGES 3
__global__ void __launch_bounds__(256) k_tgemm(
    const __nv_bfloat16* __restrict__ Ahi, const __nv_bfloat16* __restrict__ Alo,
    const __nv_bfloat16* __restrict__ Bhi, const __nv_bfloat16* __restrict__ Blo,
    const float* __restrict__ bias, float* __restrict__ C, int K, int lda, int N)
{
    extern __shared__ char smem_raw[];
    uint32_t sbase = smem_u32(smem_raw);
    uint32_t abase = (sbase + 1023u) & ~1023u;

    int tid = threadIdx.x;
    int lane = tid & 31;
    int wid = tid >> 5;
    int warp_m = wid & 1;
    int warp_n = wid >> 1;
    int row0 = blockIdx.y * 64;
    int col0 = blockIdx.x * 64;
    int NC = K >> 6;

    float acc[2][2][4];
#pragma unroll
    for (int i = 0; i < 2; i++)
#pragma unroll
        for (int j = 0; j < 2; j++)
#pragma unroll
            for (int q = 0; q < 4; q++) acc[i][j][q] = 0.0f;

    auto load_chunk = [&](int buf, int k0) {
        uint32_t bb = abase + buf * GBUF_BYTES;
#pragma unroll
        for (int i = 0; i < 2; i++) {
            int u = tid + i * 256;
            int r = u >> 3, ch = u & 7;
            uint32_t soff = SW128((uint32_t)(r * 128 + ch * 16));
            size_t goA = (size_t)(row0 + r) * lda + k0 + ch * 8;
            size_t goB = (size_t)(col0 + r) * K + k0 + ch * 8;
            CP_ASYNC16(bb + soff,          Ahi + goA);
            CP_ASYNC16(bb + 8192 + soff,   Alo + goA);
            CP_ASYNC16(bb + 16384 + soff,  Bhi + goB);
            CP_ASYNC16(bb + 24576 + soff,  Blo + goB);
        }
    };

    // prologue: fill stages 0,1 (NC >= 4 for all our shapes)
    load_chunk(0, 0);
    CP_COMMIT();
    load_chunk(1, 64);
    CP_COMMIT();

    int a_r = warp_m * 32 + (lane & 15);
    int a_csel = (lane >> 4) << 3;
    int b_r = warp_n * 16 + (lane & 7) + ((lane >> 4) << 3);
    int b_csel = ((lane >> 3) & 1) << 3;

    int buf = 0, pbuf = 2;   // compute buffer, prefetch buffer
    for (int c = 0; c < NC; c++) {
        CP_WAIT(GSTAGES - 2);          // chunk c resident
        __syncthreads();               // also: all threads done with buffer pbuf
        if (c + 2 < NC) load_chunk(pbuf, (c + 2) * 64);
        CP_COMMIT();                   // always commit (keeps group counting uniform)

        uint32_t bb = abase + buf * GBUF_BYTES;
#pragma unroll
        for (int kk = 0; kk < 4; kk++) {
            int k0 = kk * 16;
            uint32_t ah[2][4], al[2][4], bh[4], bl[4];
#pragma unroll
            for (int mf = 0; mf < 2; mf++) {
                uint32_t off = SW128((uint32_t)((a_r + mf * 16) * 128 + (k0 + a_csel) * 2));
                LDSM4(ah[mf], bb + off);
                LDSM4(al[mf], bb + 8192 + off);
            }
            {
                uint32_t off = SW128((uint32_t)(b_r * 128 + (k0 + b_csel) * 2));
                LDSM4(bh, bb + 16384 + off);
                LDSM4(bl, bb + 24576 + off);
            }
#pragma unroll
            for (int mf = 0; mf < 2; mf++) {
#pragma unroll
                for (int nf = 0; nf < 2; nf++) {
                    MMA16816(acc[mf][nf], ah[mf], bh[2 * nf], bh[2 * nf + 1]);
                    MMA16816(acc[mf][nf], ah[mf], bl[2 * nf], bl[2 * nf + 1]);
                    MMA16816(acc[mf][nf], al[mf], bh[2 * nf], bh[2 * nf + 1]);
                }
            }
        }
        buf = (buf == GSTAGES - 1) ? 0 : buf + 1;
        pbuf = (pbuf == GSTAGES - 1) ? 0 : pbuf + 1;
    }

    int gid = lane >> 2, tig = lane & 3;
#pragma unroll
    for (int mf = 0; mf < 2; mf++) {
#pragma unroll
        for (int nf = 0; nf < 2; nf++) {
            int r = row0 + warp_m * 32 + mf * 16 + gid;
            int cc = col0 + warp_n * 16 + nf * 8 + tig * 2;
            float2 b01 = *(const float2*)&bias[cc];
            float2 o0 = { acc[mf][nf][0] + b01.x, acc[mf][nf][1] + b01.y };
            float2 o1 = { acc[mf][nf][2] + b01.x, acc[mf][nf][3] + b01.y };
            *(float2*)&C[(size_t)r * N + cc] = o0;
            *(float2*)&C[(size_t)(r + 8) * N + cc] = o1;
        }
    }
}

// ================= mega prep kernel =================
// block ranges: [0]=dones, [1,10)=decay, [10,266)=obs split, [266,4362)=nlm wt,
// [4362,4618)=tsplit bb_w1, [4618,5130)=bb_w2, [5130,8202)=syn_w1, [8202,10250)=syn_w2
__device__ void tsplit_block(const float* __restrict__ W, int K, int N,
                             __nv_bfloat16* __restrict__ Ohi, __nv_bfloat16* __restrict__ Olo,
                             int local) {
    __shared__ float t[32][33];
    int ktiles = K >> 5;
    int kt = local % ktiles, nt = local / ktiles;
    int k0 = kt * 32, n0 = nt * 32;
    int tx = threadIdx.x & 31, ty = threadIdx.x >> 5;
    for (int i = ty; i < 32; i += 8)
        t[i][tx] = W[(size_t)(k0 + i) * N + n0 + tx];
    __syncthreads();
    for (int i = ty; i < 32; i += 8) {
        float v = t[tx][i];
        size_t o = (size_t)(n0 + i) * K + k0 + tx;
        __nv_bfloat16 h, l;
        split2(v, &h, &l);
        Ohi[o] = h; Olo[o] = l;
    }
}

__global__ void k_prep(const unsigned char* __restrict__ dones_raw,
                       const float* __restrict__ dp,
                       const float* __restrict__ obs,
                       const float* __restrict__ nw1, const float* __restrict__ nw2,
                       const float* __restrict__ bw1, const float* __restrict__ bw2,
                       const float* __restrict__ sw1, const float* __restrict__ sw2) {
    int bid = blockIdx.x, tid = threadIdx.x;
    if (bid == 0) {
        __shared__ int mode;
        if (tid == 0) {
            bool nzoff = false, floatlike = true, anynz = false;
            for (int i = 0; i < Bx; i++) {
                unsigned char v = dones_raw[i];
                if (v) {
                    anynz = true;
                    int r = i & 3;
                    if (r != 0) nzoff = true;
                    bool okf = (r == 2 && v == 0x80) || (r == 3 && v == 0x3F);
                    if (!okf) floatlike = false;
                }
            }
            mode = (nzoff && floatlike && anynz) ? 2 : (nzoff ? 0 : 1);
        }
        __syncthreads();
        int b = tid, m = mode, v;
        if (m == 0)      v = (dones_raw[b] != 0);
        else if (m == 1) v = (((const int*)dones_raw)[b] != 0);
        else             v = (((const float*)dones_raw)[b] != 0.0f);
        g_dones[b] = v;
    } else if (bid < 10) {
        int s = (bid - 1) * 256 + tid;
        if (s < SYNCHx) {
            float c = fminf(fmaxf(dp[s], 0.0f), 4.0f);
            float sum = 0.0f;
            for (int m = 0; m < Mx; m++) {
                float v = __expf(-(float)(Mx - 1 - m) * c);
                g_decay[m * SYNCHx + s] = v;
                sum += v;
            }
            g_invden[s] = rsqrtf(sum);
            int i = 0, base = 0;
            while (s >= base + (NSYx - i)) { base += NSYx - i; i++; }
            g_tri_i[s] = i;
            g_tri_j[s] = i + (s - base);
        }
    } else if (bid < 266) {
        int i = (bid - 10) * 256 + tid;
        split2(obs[i], &g_obshi[i], &g_obslo[i]);
    } else if (bid < 4362) {
        int idx = (bid - 266) * 256 + tid;
        int d = idx >> 10, mh = idx & 1023;
        g_w1t[idx] = nw1[mh * Dx + d];
        if (idx < Dx * 32) {
            int d2 = idx >> 5, hc = idx & 31;
            g_w2t[idx] = nw2[hc * Dx + d2];
        }
    } else if (bid < 4618) {
        tsplit_block(bw1, 256, 1024, g_wb1hi, g_wb1lo, bid - 4362);
    } else if (bid < 5130) {
        tsplit_block(bw2, 512, 1024, g_wb2hi, g_wb2lo, bid - 4618);
    } else if (bid < 8202) {
        tsplit_block(sw1, 1536, 2048, g_ws1hi, g_ws1lo, bid - 5130);
    } else {
        tsplit_block(sw2, 1024, 2048, g_ws2hi, g_ws2lo, bid - 8202);
    }
}

// ================= GLU + LN -> bf16 split (optional at-gather for iter 0) ===
__global__ void k_gluln_split(const float* __restrict__ y, int halfN,
                              const float* __restrict__ sc, const float* __restrict__ bi,
                              __nv_bfloat16* __restrict__ ohi, __nv_bfloat16* __restrict__ olo,
                              int ostride, int gather,
                              const float* __restrict__ at_in,
                              const float* __restrict__ start_at) {
    __shared__ float v[1024];
    __shared__ float red_s[8], red_q[8];
    int row = blockIdx.x, tid = threadIdx.x;
    const float* yr = y + (size_t)row * 2 * halfN;
    float sum = 0.0f, sq = 0.0f;
    for (int c = tid; c < halfN; c += 256) {
        float a = yr[c];
        float g = yr[halfN + c];
        float val = a * sigf(g);
        v[c] = val;
        sum += val;
        sq += val * val;
    }
#pragma unroll
    for (int o = 16; o > 0; o >>= 1) {
        sum += __shfl_xor_sync(0xffffffffu, sum, o);
        sq  += __shfl_xor_sync(0xffffffffu, sq, o);
    }
    int w = tid >> 5;
    if ((tid & 31) == 0) { red_s[w] = sum; red_q[w] = sq; }
    __syncthreads();
    if (tid == 0) {
        float ts = 0.0f, tq = 0.0f;
        for (int i = 0; i < 8; i++) { ts += red_s[i]; tq += red_q[i]; }
        red_s[0] = ts; red_q[0] = tq;
    }
    __syncthreads();
    float invN = 1.0f / (float)halfN;
    float mean = red_s[0] * invN;
    float var = red_q[0] * invN - mean * mean;
    float inv = rsqrtf(var + 1e-6f);
    for (int c = tid; c < halfN; c += 256) {
        float val = (v[c] - mean) * inv * sc[c] + bi[c];
        size_t o = (size_t)row * ostride + c;
        split2(val, &ohi[o], &olo[o]);
    }
    if (gather) {
        bool done = g_dones[row] != 0;
        for (int c = tid; c < Dx; c += 256) {
            float val = done ? start_at[c * 32 + 31]
                             : at_in[((size_t)(row * Dx + c)) * 32 + 31];
            size_t o = (size_t)row * ostride + halfN + c;
            split2(val, &ohi[o], &olo[o]);
        }
    }
}

// GLU + LN -> fp32 contiguous (h_st[i])
__global__ void k_gluln_f32(const float* __restrict__ y, int halfN,
                            const float* __restrict__ sc, const float* __restrict__ bi,
                            float* __restrict__ out) {
    __shared__ float v[1024];
    __shared__ float red_s[8], red_q[8];
    int row = blockIdx.x, tid = threadIdx.x;
    const float* yr = y + (size_t)row * 2 * halfN;
    float sum = 0.0f, sq = 0.0f;
    for (int c = tid; c < halfN; c += 256) {
        float a = yr[c];
        float g = yr[halfN + c];
        float val = a * sigf(g);
        v[c] = val;
        sum += val;
        sq += val * val;
    }
#pragma unroll
    for (int o = 16; o > 0; o >>= 1) {
        sum += __shfl_xor_sync(0xffffffffu, sum, o);
        sq  += __shfl_xor_sync(0xffffffffu, sq, o);
    }
    int w = tid >> 5;
    if ((tid & 31) == 0) { red_s[w] = sum; red_q[w] = sq; }
    __syncthreads();
    if (tid == 0) {
        float ts = 0.0f, tq = 0.0f;
        for (int i = 0; i < 8; i++) { ts += red_s[i]; tq += red_q[i]; }
        red_s[0] = ts; red_q[0] = tq;
    }
    __syncthreads();
    float invN = 1.0f / (float)halfN;
    float mean = red_s[0] * invN;
    float var = red_q[0] * invN - mean * mean;
    float inv = rsqrtf(var + 1e-6f);
    for (int c = tid; c < halfN; c += 256)
        out[(size_t)row * halfN + c] = (v[c] - mean) * inv * sc[c] + bi[c];
}

// ================= NLM (templated on iteration) =================
// block = 8 warps, warp w -> d = d0+w; lanes = 32 b per chunk, 8 chunks.
template<int IT>
__global__ void __launch_bounds__(256) k_nlm(
    const float* __restrict__ st_in, const float* __restrict__ start_st,
    const float* __restrict__ b1, const float* __restrict__ T1,
    const float* __restrict__ b2, const float* __restrict__ T2) {
    __shared__ float4 w1v[8][256];
    __shared__ float w2s[8][32], b1s[8][32], b2s[8][2];
    __shared__ float hsm[IT + 1][32][9];
    __shared__ float xsm[32][9];
    __shared__ float invT[2];
    int tid = threadIdx.x;
    int w = tid >> 5, lane = tid & 31;
    int d0 = blockIdx.x * 8;
    for (int u = tid; u < 2048; u += 256) {
        int dl = u >> 8, q = u & 255;
        w1v[dl][q] = ((const float4*)g_w1t)[(size_t)(d0 + dl) * 256 + q];
    }
    {
        int dl = w, h = lane;
        w2s[dl][h] = g_w2t[(d0 + dl) * 32 + h];
        b1s[dl][h] = b1[(d0 + dl) * 32 + h];
    }
    if (tid < 16) b2s[tid >> 1][tid & 1] = b2[(d0 + (tid >> 1)) * 2 + (tid & 1)];
    if (tid == 0) { invT[0] = 1.0f / T1[0]; invT[1] = 1.0f / T2[0]; }
    __syncthreads();
    float iT1 = invT[0], iT2 = invT[1];
    int d = d0 + w;

    for (int ch = 0; ch < 8; ch++) {
        if (tid < (IT + 1) * 64) {
            int j = tid >> 6, rem = tid & 63, bl = rem >> 1, hf = rem & 1;
            float4 hv = *(const float4*)&g_hst[j][(size_t)(ch * 32 + bl) * Dx + d0 + hf * 4];
            hsm[j][bl][hf * 4 + 0] = hv.x;
            hsm[j][bl][hf * 4 + 1] = hv.y;
            hsm[j][bl][hf * 4 + 2] = hv.z;
            hsm[j][bl][hf * 4 + 3] = hv.w;
        }
        __syncthreads();
        int b = ch * 32 + lane;
        const float* stp = g_dones[b] ? (start_st + d * 32)
                                      : (st_in + ((size_t)(b << 10) + d) * 32);
        float sin[32];
#pragma unroll
        for (int q = 0; q < 8; q++) {
            float4 t4 = ((const float4*)stp)[q];
            sin[q * 4 + 0] = t4.x; sin[q * 4 + 1] = t4.y;
            sin[q * 4 + 2] = t4.z; sin[q * 4 + 3] = t4.w;
        }
        float hreg[IT + 1];
#pragma unroll
        for (int j = 0; j <= IT; j++) hreg[j] = hsm[j][lane][w];

        float x[32];
#pragma unroll
        for (int h = 0; h < 32; h++) x[h] = b1s[w][h];
#pragma unroll
        for (int m = 0; m < 32; m++) {
            float a = (m < 31 - IT) ? sin[m + IT + 1] : hreg[m - (31 - IT)];
#pragma unroll
            for (int q = 0; q < 8; q++) {
                float4 wv = w1v[w][m * 8 + q];
                x[q * 4 + 0] += a * wv.x;
                x[q * 4 + 1] += a * wv.y;
                x[q * 4 + 2] += a * wv.z;
                x[q * 4 + 3] += a * wv.w;
            }
        }
        float y0 = b2s[w][0], y1 = b2s[w][1];
#pragma unroll
        for (int h = 0; h < 16; h++) {
            float u = (x[h] * iT1) * sigf(x[h + 16] * iT1);
            y0 += u * w2s[w][h * 2 + 0];
            y1 += u * w2s[w][h * 2 + 1];
        }
        float r = (y0 * iT2) * sigf(y1 * iT2);
        g_hat[IT][(size_t)d * Bx + b] = r;
        if (IT < 3) {
            xsm[lane][w] = r;
            __syncthreads();
            int bl = tid >> 3, dl = tid & 7;
            float vv = xsm[bl][dl];
            __nv_bfloat16 hh, ll;
            split2(vv, &hh, &ll);
            size_t o = (size_t)(ch * 32 + bl) * (DINx + Dx) + DINx + d0 + dl;
            g_prehi[o] = hh; g_prelo[o] = ll;
        }
        __syncthreads();
    }
}

// ================= final assembly + synchrony (one launch) =================
__global__ void k_fin(float* __restrict__ out,
                      const float* __restrict__ st_in, const float* __restrict__ at_in,
                      const float* __restrict__ start_st, const float* __restrict__ start_at) {
    int tid = threadIdx.x;
    if (blockIdx.x < 1024) {
        // assembly: tile = 8 d x 32 b
        __shared__ float hsm[4][32][9];
        int local = blockIdx.x;
        int dt = local & 127, bt = local >> 7;
        int d0 = dt * 8, b0 = bt * 32;
        {
            int j = tid >> 6, rem = tid & 63, bl = rem >> 1, hf = rem & 1;
            float4 hv = *(const float4*)&g_hst[j][(size_t)(b0 + bl) * Dx + d0 + hf * 4];
            hsm[j][bl][hf * 4 + 0] = hv.x;
            hsm[j][bl][hf * 4 + 1] = hv.y;
            hsm[j][bl][hf * 4 + 2] = hv.z;
            hsm[j][bl][hf * 4 + 3] = hv.w;
        }
        __syncthreads();
        int w = tid >> 5, lane = tid & 31;
        int d = d0 + w, b = b0 + lane;
        bool done = g_dones[b] != 0;
        const float* stp = done ? (start_st + d * 32) : (st_in + ((size_t)(b << 10) + d) * 32);
        const float* atp = done ? (start_at + d * 32) : (at_in + ((size_t)(b << 10) + d) * 32);
        float so[32], ao[32];
#pragma unroll
        for (int q = 1; q < 8; q++) {
            float4 t4 = ((const float4*)stp)[q];
            so[q * 4 - 4] = t4.x; so[q * 4 - 3] = t4.y; so[q * 4 - 2] = t4.z; so[q * 4 - 1] = t4.w;
            float4 u4 = ((const float4*)atp)[q];
            ao[q * 4 - 4] = u4.x; ao[q * 4 - 3] = u4.y; ao[q * 4 - 2] = u4.z; ao[q * 4 - 1] = u4.w;
        }
#pragma unroll
        for (int j = 0; j < 4; j++) {
            so[28 + j] = hsm[j][lane][w];
            ao[28 + j] = g_hat[j][(size_t)d * Bx + b];
        }
        float* o1 = out + ((size_t)(b << 10) + d) * 32;
        float* o2 = o1 + BDMx;
#pragma unroll
        for (int q = 0; q < 8; q++) {
            float4 v1 = { so[q * 4], so[q * 4 + 1], so[q * 4 + 2], so[q * 4 + 3] };
            float4 v2 = { ao[q * 4], ao[q * 4 + 1], ao[q * 4 + 2], ao[q * 4 + 3] };
            ((float4*)o1)[q] = v1;
            ((float4*)o2)[q] = v2;
        }
    } else {
        // synchrony
        __shared__ float S[Mx * NSYx];   // [m][j]
        int b = blockIdx.x - 1024;
        bool done = g_dones[b] != 0;
        float* outs = out + 2 * (size_t)BDMx;
        for (int t = tid; t < Mx * NSYx; t += 256) {
            int m = t & 31, j = t >> 5;
            int dd = Dx - NSYx + j;
            float val;
            if (m < 28)
                val = done ? start_at[dd * 32 + m + 4]
                           : at_in[((size_t)(b * Dx + dd)) * 32 + m + 4];
            else
                val = g_hat[m - 28][(size_t)dd * Bx + b];
            S[m * NSYx + j] = val;
        }
        __syncthreads();
        for (int s = tid; s < SYNCHx; s += 256) {
            int ti = g_tri_i[s], tj = g_tri_j[s];
            float acc = 0.0f;
#pragma unroll
            for (int m = 0; m < Mx; m++)
                acc += g_decay[m * SYNCHx + s] * S[m * NSYx + ti] * S[m * NSYx + tj];
            outs[(size_t)b * SYNCHx + s] = acc * g_invden[s];
        }
    }
}

// =====================================================================
extern "C" void kernel_launch(void* const* d_in, const int* in_sizes, int n_in,
                              void* d_out, int out_size) {
    (void)in_sizes; (void)n_in; (void)out_size;
    const float* obs      = (const float*)d_in[0];
    const unsigned char* dones_raw = (const unsigned char*)d_in[1];
    const float* st_in    = (const float*)d_in[3];
    const float* at_in    = (const float*)d_in[4];
    const float* start_st = (const float*)d_in[5];
    const float* start_at = (const float*)d_in[6];
    const float* bb_w1    = (const float*)d_in[7];
    const float* bb_b1    = (const float*)d_in[8];
    const float* ln1s     = (const float*)d_in[9];
    const float* ln1b     = (const float*)d_in[10];
    const float* bb_w2    = (const float*)d_in[11];
    const float* bb_b2    = (const float*)d_in[12];
    const float* ln2s     = (const float*)d_in[13];
    const float* ln2b     = (const float*)d_in[14];
    const float* syn_w1   = (const float*)d_in[15];
    const float* syn_b1   = (const float*)d_in[16];
    const float* sln1s    = (const float*)d_in[17];
    const float* sln1b    = (const float*)d_in[18];
    const float* syn_w2   = (const float*)d_in[19];
    const float* syn_b2   = (const float*)d_in[20];
    const float* sln2s    = (const float*)d_in[21];
    const float* sln2b    = (const float*)d_in[22];
    const float* nlm1_w   = (const float*)d_in[23];
    const float* nlm1_b   = (const float*)d_in[24];
    const float* nlm1_T   = (const float*)d_in[25];
    const float* nlm2_w   = (const float*)d_in[26];
    const float* nlm2_b   = (const float*)d_in[27];
    const float* nlm2_T   = (const float*)d_in[28];
    const float* decay_p  = (const float*)d_in[29];
    float* out = (float*)d_out;

    void *p_y, *p_hst;
    void *p_obshi, *p_obslo, *p_prehi, *p_prelo, *p_h1hi, *p_h1lo;
    void *p_wb1h, *p_wb1l, *p_wb2h, *p_wb2l, *p_ws1h, *p_ws1l, *p_ws2h, *p_ws2l;
    cudaGetSymbolAddress(&p_y, g_y);
    cudaGetSymbolAddress(&p_hst, g_hst);
    cudaGetSymbolAddress(&p_obshi, g_obshi);  cudaGetSymbolAddress(&p_obslo, g_obslo);
    cudaGetSymbolAddress(&p_prehi, g_prehi);  cudaGetSymbolAddress(&p_prelo, g_prelo);
    cudaGetSymbolAddress(&p_h1hi, g_h1hi);    cudaGetSymbolAddress(&p_h1lo, g_h1lo);
    cudaGetSymbolAddress(&p_wb1h, g_wb1hi);   cudaGetSymbolAddress(&p_wb1l, g_wb1lo);
    cudaGetSymbolAddress(&p_wb2h, g_wb2hi);   cudaGetSymbolAddress(&p_wb2l, g_wb2lo);
    cudaGetSymbolAddress(&p_ws1h, g_ws1hi);   cudaGetSymbolAddress(&p_ws1l, g_ws1lo);
    cudaGetSymbolAddress(&p_ws2h, g_ws2hi);   cudaGetSymbolAddress(&p_ws2l, g_ws2lo);
    float* gy   = (float*)p_y;
    float* ghst = (float*)p_hst;

    static int smem_set = 0;
    int gsmem = GSTAGES * GBUF_BYTES + 1024;
    if (!smem_set) {
        cudaFuncSetAttribute(k_tgemm, cudaFuncAttributeMaxDynamicSharedMemorySize, gsmem);
        smem_set = 1;
    }

    // prep (1 launch)
    k_prep<<<10250, 256>>>(dones_raw, decay_p, obs, nlm1_w, nlm2_w,
                           bb_w1, bb_w2, syn_w1, syn_w2);

    // backbone (4 launches); f1 reuses h1 buffers
    k_tgemm<<<dim3(16, 4), 256, gsmem>>>(
        (const __nv_bfloat16*)p_obshi, (const __nv_bfloat16*)p_obslo,
        (const __nv_bfloat16*)p_wb1h, (const __nv_bfloat16*)p_wb1l,
        bb_b1, gy, 256, 256, 1024);
    k_gluln_split<<<Bx, 256>>>(gy, 512, ln1s, ln1b,
        (__nv_bfloat16*)p_h1hi, (__nv_bfloat16*)p_h1lo, 512, 0, nullptr, nullptr);
    k_tgemm<<<dim3(16, 4), 256, gsmem>>>(
        (const __nv_bfloat16*)p_h1hi, (const __nv_bfloat16*)p_h1lo,
        (const __nv_bfloat16*)p_wb2h, (const __nv_bfloat16*)p_wb2l,
        bb_b2, gy, 512, 512, 1024);
    k_gluln_split<<<Bx, 256>>>(gy, 512, ln2s, ln2b,
        (__nv_bfloat16*)p_prehi, (__nv_bfloat16*)p_prelo, 1536, 1, at_in, start_at);

    for (int i = 0; i < ITERSx; i++) {
        k_tgemm<<<dim3(32, 4), 256, gsmem>>>(
            (const __nv_bfloat16*)p_prehi, (const __nv_bfloat16*)p_prelo,
            (const __nv_bfloat16*)p_ws1h, (const __nv_bfloat16*)p_ws1l,
            syn_b1, gy, 1536, 1536, 2048);
        k_gluln_split<<<Bx, 256>>>(gy, 1024, sln1s, sln1b,
            (__nv_bfloat16*)p_h1hi, (__nv_bfloat16*)p_h1lo, 1024, 0, nullptr, nullptr);
        k_tgemm<<<dim3(32, 4), 256, gsmem>>>(
            (const __nv_bfloat16*)p_h1hi, (const __nv_bfloat16*)p_h1lo,
            (const __nv_bfloat16*)p_ws2h, (const __nv_bfloat16*)p_ws2l,
            syn_b2, gy, 1024, 1024, 2048);
        k_gluln_f32<<<Bx, 256>>>(gy, 1024, sln2s, sln2b, ghst + (size_t)i * BDx);
        switch (i) {
            case 0: k_nlm<0><<<128, 256>>>(st_in, start_st, nlm1_b, nlm1_T, nlm2_b, nlm2_T); break;
            case 1: k_nlm<1><<<128, 256>>>(st_in, start_st, nlm1_b, nlm1_T, nlm2_b, nlm2_T); break;
            case 2: k_nlm<2><<<128, 256>>>(st_in, start_st, nlm1_b, nlm1_T, nlm2_b, nlm2_T); break;
            case 3: k_nlm<3><<<128, 256>>>(st_in, start_st, nlm1_b, nlm1_T, nlm2_b, nlm2_T); break;
        }
    }

    k_fin<<<1024 + Bx, 256>>>(out, st_in, at_in, start_st, start_at);
}